// round 3
// baseline (speedup 1.0000x reference)
#include <cuda_runtime.h>

// ---------------- Problem constants ----------------
#define T_TOK 16384        // B*S tokens
#define DM    512
#define DFF   2048
#define HN    8
#define DKV   64
#define SQ    512
#define BATCH 32
#define NLAYER 6
#define EPSBN 1e-5f

// ---------------- Static device scratch ----------------
__device__ float g_X[(size_t)T_TOK * DM];           // activations
__device__ float g_Y[(size_t)T_TOK * DM];           // pre-BN temp
__device__ float g_Q[(size_t)T_TOK * DM];           // [H][T][64]
__device__ float g_K[(size_t)T_TOK * DM];
__device__ float g_V[(size_t)T_TOK * DM];
__device__ float g_ATT[(size_t)T_TOK * DM];         // [t][h*64+v]
__device__ float g_FFH[(size_t)T_TOK * DFF];
__device__ float g_SC[(size_t)BATCH * HN * SQ * SQ];// [h][b][s][t]
__device__ float g_partS[256 * DM];
__device__ float g_partQ[256 * DM];
__device__ float g_nrm[2 * DM];

// ---------------- Generic SIMT GEMM with f32x2 packed FMA ----------------
// C = alpha * A @ B(^T if TRB) (+bias) (+residual) (ReLU optional)
// A: row-major [M,K] lda ; B: NN row-major [K,N] ldb / NT row-major [N,K] ldb
// Batched via blockIdx.z: zo = z/zInner, zi = z%zInner; offsets = zo*s?o + zi*s?i
template <int BM, int BN, int BK, int TM, int TN, bool TRB, bool BIAS, bool RELU, bool RES>
__global__ void __launch_bounds__((BM / TM) * (BN / TN))
gemm_k(const float* __restrict__ Ag, const float* __restrict__ Bg,
       float* __restrict__ Cg, const float* __restrict__ Rg,
       const float* __restrict__ biasg,
       int K, int lda, int ldb, int ldc, float alpha, int zInner,
       long long sAo, long long sAi, long long sBo, long long sBi,
       long long sCo, long long sCi) {
  constexpr int NTHR = (BM / TM) * (BN / TN);
  const int tid = threadIdx.x;
  const int zo = blockIdx.z / zInner;
  const int zi = blockIdx.z % zInner;

  const float* A = Ag + zo * sAo + zi * sAi + (long long)blockIdx.x * BM * lda;
  const float* B = Bg + zo * sBo + zi * sBi;
  if (TRB) B += (long long)blockIdx.y * BN * ldb;
  else     B += (long long)blockIdx.y * BN;
  long long coff = zo * sCo + zi * sCi + (long long)blockIdx.x * BM * ldc +
                   (long long)blockIdx.y * BN;
  float* C = Cg + coff;
  const float* R = RES ? (Rg + coff) : nullptr;

  __shared__ __align__(16) float As[BK][BM];
  __shared__ __align__(16) float Bs[BK][BN];

  const int tCol = tid % (BN / TN);
  const int tRow = tid / (BN / TN);

  unsigned long long acc[TM][TN / 2];
#pragma unroll
  for (int i = 0; i < TM; i++)
#pragma unroll
    for (int j = 0; j < TN / 2; j++) acc[i][j] = 0ULL;

  // A loader: BM x BK tile, float4 along K
  const int aCol = tid % (BK / 4);
  const int aRow0 = tid / (BK / 4);
  constexpr int aStride = NTHR / (BK / 4);
  // B loader NN: BK x BN tile, float4 along N
  const int bCol = tid % (BN / 4);
  const int bRow0 = tid / (BN / 4);
  constexpr int bStride = NTHR / (BN / 4);
  // B loader NT: BN rows x BK cols, float4 along K
  const int cCol = tid % (BK / 4);
  const int cRow0 = tid / (BK / 4);
  constexpr int cStride = NTHR / (BK / 4);

  for (int k0 = 0; k0 < K; k0 += BK) {
#pragma unroll
    for (int it = 0; it < BM / aStride; ++it) {
      int r = aRow0 + it * aStride;
      float4 v = *reinterpret_cast<const float4*>(&A[(long long)r * lda + k0 + aCol * 4]);
      As[aCol * 4 + 0][r] = v.x;
      As[aCol * 4 + 1][r] = v.y;
      As[aCol * 4 + 2][r] = v.z;
      As[aCol * 4 + 3][r] = v.w;
    }
    if (!TRB) {
#pragma unroll
      for (int it = 0; it < BK / bStride; ++it) {
        int r = bRow0 + it * bStride;
        float4 v = *reinterpret_cast<const float4*>(&B[(long long)(k0 + r) * ldb + bCol * 4]);
        *reinterpret_cast<float4*>(&Bs[r][bCol * 4]) = v;
      }
    } else {
#pragma unroll
      for (int it = 0; it < BN / cStride; ++it) {
        int n = cRow0 + it * cStride;
        float4 v = *reinterpret_cast<const float4*>(&B[(long long)n * ldb + k0 + cCol * 4]);
        Bs[cCol * 4 + 0][n] = v.x;
        Bs[cCol * 4 + 1][n] = v.y;
        Bs[cCol * 4 + 2][n] = v.z;
        Bs[cCol * 4 + 3][n] = v.w;
      }
    }
    __syncthreads();

#pragma unroll
    for (int k = 0; k < BK; k++) {
      float a[TM];
#pragma unroll
      for (int i = 0; i < TM; i += 4) {
        float4 v = *reinterpret_cast<const float4*>(&As[k][tRow * TM + i]);
        a[i] = v.x; a[i + 1] = v.y; a[i + 2] = v.z; a[i + 3] = v.w;
      }
      unsigned long long aa[TM];
#pragma unroll
      for (int i = 0; i < TM; i++)
        asm("mov.b64 %0, {%1, %1};" : "=l"(aa[i]) : "f"(a[i]));
      unsigned long long bb[TN / 2];
#pragma unroll
      for (int j = 0; j < TN / 2; j++)
        bb[j] = *reinterpret_cast<const unsigned long long*>(&Bs[k][tCol * TN + 2 * j]);
#pragma unroll
      for (int i = 0; i < TM; i++)
#pragma unroll
        for (int j = 0; j < TN / 2; j++)
          asm("fma.rn.f32x2 %0, %1, %2, %0;" : "+l"(acc[i][j]) : "l"(aa[i]), "l"(bb[j]));
    }
    __syncthreads();
  }

  // epilogue
#pragma unroll
  for (int i = 0; i < TM; i++) {
    int row = tRow * TM + i;
#pragma unroll
    for (int j = 0; j < TN / 2; j++) {
      int col = tCol * TN + 2 * j;
      float2 v = *reinterpret_cast<float2*>(&acc[i][j]);
      float x0 = v.x * alpha, x1 = v.y * alpha;
      if (BIAS) {
        x0 += biasg[(long long)blockIdx.y * BN + col];
        x1 += biasg[(long long)blockIdx.y * BN + col + 1];
      }
      if (RES) {
        float2 r2 = *reinterpret_cast<const float2*>(&R[(long long)row * ldc + col]);
        x0 += r2.x; x1 += r2.y;
      }
      if (RELU) { x0 = fmaxf(x0, 0.f); x1 = fmaxf(x1, 0.f); }
      *reinterpret_cast<float2*>(&C[(long long)row * ldc + col]) = make_float2(x0, x1);
    }
  }
}

// ---------------- Elementwise kernels ----------------
__global__ void embed_k(const int* __restrict__ tok, const float* __restrict__ emb,
                        float* __restrict__ X) {
  int t = blockIdx.x;
  int c4 = threadIdx.x;  // 128 threads, float4 each
  int tk = tok[t];
  float4 v = reinterpret_cast<const float4*>(emb + (long long)tk * DM)[c4];
  v.x *= 8.f; v.y *= 8.f; v.z *= 8.f; v.w *= 8.f;
  reinterpret_cast<float4*>(X + (long long)t * DM)[c4] = v;
}

__global__ void softmax512_k(float* __restrict__ S) {
  int warp = threadIdx.x >> 5, lane = threadIdx.x & 31;
  long long row = (long long)blockIdx.x * 8 + warp;
  float* p = S + row * 512;
  float4 v[4];
  float mx = -1e30f;
#pragma unroll
  for (int it = 0; it < 4; it++) {
    v[it] = *reinterpret_cast<const float4*>(p + it * 128 + lane * 4);
    mx = fmaxf(mx, fmaxf(fmaxf(v[it].x, v[it].y), fmaxf(v[it].z, v[it].w)));
  }
#pragma unroll
  for (int off = 16; off; off >>= 1) mx = fmaxf(mx, __shfl_xor_sync(0xffffffffu, mx, off));
  float sum = 0.f;
#pragma unroll
  for (int it = 0; it < 4; it++) {
    v[it].x = __expf(v[it].x - mx);
    v[it].y = __expf(v[it].y - mx);
    v[it].z = __expf(v[it].z - mx);
    v[it].w = __expf(v[it].w - mx);
    sum += v[it].x + v[it].y + v[it].z + v[it].w;
  }
#pragma unroll
  for (int off = 16; off; off >>= 1) sum += __shfl_xor_sync(0xffffffffu, sum, off);
  float inv = 1.f / sum;
#pragma unroll
  for (int it = 0; it < 4; it++) {
    v[it].x *= inv; v[it].y *= inv; v[it].z *= inv; v[it].w *= inv;
    *reinterpret_cast<float4*>(p + it * 128 + lane * 4) = v[it];
  }
}

__global__ void bn_part_k(const float* __restrict__ Y, float* __restrict__ pS,
                          float* __restrict__ pQ) {
  int c = threadIdx.x;           // 512
  int p = blockIdx.x;            // 256 blocks * 64 rows
  const float* base = Y + (long long)p * 64 * DM + c;
  float s = 0.f, q = 0.f;
#pragma unroll 8
  for (int r = 0; r < 64; r++) {
    float v = base[(long long)r * DM];
    s += v;
    q += v * v;
  }
  pS[p * DM + c] = s;
  pQ[p * DM + c] = q;
}

__global__ void bn_finish_k(const float* __restrict__ pS, const float* __restrict__ pQ,
                            const float* __restrict__ g, const float* __restrict__ be,
                            float* __restrict__ nrm) {
  int c = threadIdx.x;  // 512
  float s = 0.f, q = 0.f;
  for (int p = 0; p < 256; p++) {
    s += pS[p * DM + c];
    q += pQ[p * DM + c];
  }
  const float invN = 1.f / (float)T_TOK;
  float mean = s * invN;
  float var = q * invN - mean * mean;
  float a = g[c] * rsqrtf(var + EPSBN);
  nrm[c] = a;
  nrm[DM + c] = be[c] - mean * a;
}

__global__ void bn_apply_k(const float* __restrict__ Y, const float* __restrict__ nrm,
                           float* __restrict__ X) {
  long long idx = ((long long)blockIdx.x * blockDim.x + threadIdx.x) * 4;
  int c = (int)(idx & (DM - 1));
  float4 v = *reinterpret_cast<const float4*>(Y + idx);
  float4 o;
  o.x = v.x * nrm[c + 0] + nrm[DM + c + 0];
  o.y = v.y * nrm[c + 1] + nrm[DM + c + 1];
  o.z = v.z * nrm[c + 2] + nrm[DM + c + 2];
  o.w = v.w * nrm[c + 3] + nrm[DM + c + 3];
  *reinterpret_cast<float4*>(X + idx) = o;
}

__global__ void copy_k(const float* __restrict__ X, float* __restrict__ out) {
  long long idx = ((long long)blockIdx.x * blockDim.x + threadIdx.x) * 4;
  *reinterpret_cast<float4*>(out + idx) = *reinterpret_cast<const float4*>(X + idx);
}

// ---------------- Host launcher ----------------
extern "C" void kernel_launch(void* const* d_in, const int* in_sizes, int n_in,
                              void* d_out, int out_size) {
  (void)in_sizes; (void)n_in; (void)out_size;
  const int*   tokens = (const int*)d_in[0];
  const float* emb = (const float*)d_in[1];
  const float* WQ  = (const float*)d_in[2];
  const float* WK  = (const float*)d_in[3];
  const float* WV  = (const float*)d_in[4];
  const float* WO  = (const float*)d_in[5];
  const float* g1  = (const float*)d_in[6];
  const float* be1 = (const float*)d_in[7];
  const float* W1  = (const float*)d_in[8];
  const float* b1  = (const float*)d_in[9];
  const float* W2  = (const float*)d_in[10];
  const float* b2  = (const float*)d_in[11];
  const float* g2  = (const float*)d_in[12];
  const float* be2 = (const float*)d_in[13];
  float* out = (float*)d_out;

  void *pX, *pY, *pQ, *pK, *pV, *pATT, *pFFH, *pSC, *ppS, *ppQ, *pnrm;
  cudaGetSymbolAddress(&pX, g_X);
  cudaGetSymbolAddress(&pY, g_Y);
  cudaGetSymbolAddress(&pQ, g_Q);
  cudaGetSymbolAddress(&pK, g_K);
  cudaGetSymbolAddress(&pV, g_V);
  cudaGetSymbolAddress(&pATT, g_ATT);
  cudaGetSymbolAddress(&pFFH, g_FFH);
  cudaGetSymbolAddress(&pSC, g_SC);
  cudaGetSymbolAddress(&ppS, g_partS);
  cudaGetSymbolAddress(&ppQ, g_partQ);
  cudaGetSymbolAddress(&pnrm, g_nrm);
  float *X = (float*)pX, *Y = (float*)pY, *Q = (float*)pQ, *Kb = (float*)pK,
        *V = (float*)pV, *ATT = (float*)pATT, *FFH = (float*)pFFH, *SC = (float*)pSC;
  float *partS = (float*)ppS, *partQ = (float*)ppQ, *nrm = (float*)pnrm;

  const long long TD64 = (long long)T_TOK * DKV;   // per-head Q/K/V stride
  const long long S64 = (long long)SQ * DKV;       // per-batch within head
  const long long SS = (long long)SQ * SQ;

  // Embed
  embed_k<<<T_TOK, 128>>>(tokens, emb, X);

  for (int i = 0; i < NLAYER; i++) {
    const float* wq = WQ + (long long)i * HN * DM * DKV;
    const float* wk = WK + (long long)i * HN * DM * DKV;
    const float* wv = WV + (long long)i * HN * DM * DKV;
    const float* wo = WO + (long long)i * DM * DM;
    const float* w1 = W1 + (long long)i * DM * DFF;
    const float* w2 = W2 + (long long)i * DFF * DM;

    // QKV projections: per-head GEMM  [T,512] @ [512,64]  (batched over h)
    gemm_k<128, 64, 16, 8, 8, false, false, false, false><<<dim3(T_TOK / 128, 1, HN), 128>>>(
        X, wq, Q, nullptr, nullptr, DM, DM, DKV, DKV, 1.f,
        HN, 0, 0, 0, (long long)DM * DKV, 0, TD64);
    gemm_k<128, 64, 16, 8, 8, false, false, false, false><<<dim3(T_TOK / 128, 1, HN), 128>>>(
        X, wk, Kb, nullptr, nullptr, DM, DM, DKV, DKV, 1.f,
        HN, 0, 0, 0, (long long)DM * DKV, 0, TD64);
    gemm_k<128, 64, 16, 8, 8, false, false, false, false><<<dim3(T_TOK / 128, 1, HN), 128>>>(
        X, wv, V, nullptr, nullptr, DM, DM, DKV, DKV, 1.f,
        HN, 0, 0, 0, (long long)DM * DKV, 0, TD64);

    // scores[h,b] = Q[h,b] @ K[h,b]^T / 8   (NT, batched over h*b)
    gemm_k<128, 128, 16, 8, 8, true, false, false, false><<<dim3(4, 4, HN * BATCH), 256>>>(
        Q, Kb, SC, nullptr, nullptr, DKV, DKV, DKV, SQ, 0.125f,
        BATCH, TD64, S64, TD64, S64, (long long)BATCH * SS, SS);

    // softmax over keys
    softmax512_k<<<(HN * BATCH * SQ) / 8, 256>>>(SC);

    // out[h,b] = P @ V[h,b]  -> ATT[t][h*64+v]
    gemm_k<128, 64, 16, 8, 8, false, false, false, false><<<dim3(4, 1, HN * BATCH), 128>>>(
        SC, V, ATT, nullptr, nullptr, SQ, SQ, DKV, DM, 1.f,
        BATCH, (long long)BATCH * SS, SS, TD64, S64, (long long)DKV, (long long)SQ * DM);

    // O projection + residual: Y = X + ATT @ WO
    gemm_k<128, 128, 16, 8, 8, false, false, false, true><<<dim3(T_TOK / 128, 4, 1), 256>>>(
        ATT, wo, Y, X, nullptr, DM, DM, DM, DM, 1.f, 1, 0, 0, 0, 0, 0, 0);

    // BatchNorm1 -> X
    bn_part_k<<<256, DM>>>(Y, partS, partQ);
    bn_finish_k<<<1, DM>>>(partS, partQ, g1 + (long long)i * DM, be1 + (long long)i * DM, nrm);
    bn_apply_k<<<(T_TOK * DM) / 1024, 256>>>(Y, nrm, X);

    // FF1: FFH = relu(X @ W1 + b1)
    gemm_k<128, 128, 16, 8, 8, false, true, true, false><<<dim3(T_TOK / 128, DFF / 128, 1), 256>>>(
        X, w1, FFH, nullptr, b1 + (long long)i * DFF, DM, DM, DFF, DFF, 1.f,
        1, 0, 0, 0, 0, 0, 0);

    // FF2: Y = X + FFH @ W2 + b2
    gemm_k<128, 128, 16, 8, 8, false, true, false, true><<<dim3(T_TOK / 128, 4, 1), 256>>>(
        FFH, w2, Y, X, b2 + (long long)i * DM, DFF, DFF, DM, DM, 1.f,
        1, 0, 0, 0, 0, 0, 0);

    // BatchNorm2 -> X
    bn_part_k<<<256, DM>>>(Y, partS, partQ);
    bn_finish_k<<<1, DM>>>(partS, partQ, g2 + (long long)i * DM, be2 + (long long)i * DM, nrm);
    bn_apply_k<<<(T_TOK * DM) / 1024, 256>>>(Y, nrm, X);
  }

  copy_k<<<(T_TOK * DM) / 1024, 256>>>(X, out);
}

// round 6
// speedup vs baseline: 1.5945x; 1.5945x over previous
#include <cuda_runtime.h>

// ---------------- Problem constants ----------------
#define T_TOK 16384        // B*S tokens
#define DM    512
#define DFF   2048
#define HN    8
#define DKV   64
#define SQ    512
#define BATCH 32
#define NLAYER 6
#define EPSBN 1e-5f

// ---------------- Static device scratch ----------------
__device__ float g_X[(size_t)T_TOK * DM];           // activations
__device__ float g_Y[(size_t)T_TOK * DM];           // pre-BN temp
__device__ float g_Q[(size_t)T_TOK * DM];           // [H][T][64]
__device__ float g_K[(size_t)T_TOK * DM];
__device__ float g_V[(size_t)T_TOK * DM];
__device__ float g_ATT[(size_t)T_TOK * DM];         // [t][h*64+v]
__device__ float g_FFH[(size_t)T_TOK * DFF];
__device__ float g_SC[(size_t)BATCH * HN * SQ * SQ];// [h][b][s][t]
__device__ float g_partS[256 * DM];
__device__ float g_partQ[256 * DM];
__device__ float g_nrm[2 * DM];

// ---------------- Generic SIMT GEMM with f32x2 packed FMA ----------------
// C = alpha * A @ B(^T if TRB) (+bias) (+residual) (ReLU optional)
// A: row-major [M,K] lda ; B: NN row-major [K,N] ldb / NT row-major [N,K] ldb
// Batched via blockIdx.z: zo = z/zInner, zi = z%zInner; offsets = zo*s?o + zi*s?i
template <int BM, int BN, int BK, int TM, int TN, bool TRB, bool BIAS, bool RELU, bool RES>
__global__ void __launch_bounds__((BM / TM) * (BN / TN))
gemm_k(const float* __restrict__ Ag, const float* __restrict__ Bg,
       float* __restrict__ Cg, const float* __restrict__ Rg,
       const float* __restrict__ biasg,
       int K, int lda, int ldb, int ldc, float alpha, int zInner,
       long long sAo, long long sAi, long long sBo, long long sBi,
       long long sCo, long long sCi) {
  constexpr int NTHR = (BM / TM) * (BN / TN);
  const int tid = threadIdx.x;
  const int zo = blockIdx.z / zInner;
  const int zi = blockIdx.z % zInner;

  const float* A = Ag + zo * sAo + zi * sAi + (long long)blockIdx.x * BM * lda;
  const float* B = Bg + zo * sBo + zi * sBi;
  if (TRB) B += (long long)blockIdx.y * BN * ldb;
  else     B += (long long)blockIdx.y * BN;
  long long coff = zo * sCo + zi * sCi + (long long)blockIdx.x * BM * ldc +
                   (long long)blockIdx.y * BN;
  float* C = Cg + coff;
  const float* R = RES ? (Rg + coff) : nullptr;

  __shared__ __align__(16) float As[BK][BM];
  __shared__ __align__(16) float Bs[BK][BN];

  const int tCol = tid % (BN / TN);
  const int tRow = tid / (BN / TN);

  unsigned long long acc[TM][TN / 2];
#pragma unroll
  for (int i = 0; i < TM; i++)
#pragma unroll
    for (int j = 0; j < TN / 2; j++) acc[i][j] = 0ULL;

  // A loader: BM x BK tile, float4 along K
  const int aCol = tid % (BK / 4);
  const int aRow0 = tid / (BK / 4);
  constexpr int aStride = NTHR / (BK / 4);
  // B loader NN: BK x BN tile, float4 along N
  const int bCol = tid % (BN / 4);
  const int bRow0 = tid / (BN / 4);
  constexpr int bStride = NTHR / (BN / 4);
  // B loader NT: BN rows x BK cols, float4 along K
  const int cCol = tid % (BK / 4);
  const int cRow0 = tid / (BK / 4);
  constexpr int cStride = NTHR / (BK / 4);

  for (int k0 = 0; k0 < K; k0 += BK) {
#pragma unroll
    for (int it = 0; it < BM / aStride; ++it) {
      int r = aRow0 + it * aStride;
      float4 v = *reinterpret_cast<const float4*>(&A[(long long)r * lda + k0 + aCol * 4]);
      As[aCol * 4 + 0][r] = v.x;
      As[aCol * 4 + 1][r] = v.y;
      As[aCol * 4 + 2][r] = v.z;
      As[aCol * 4 + 3][r] = v.w;
    }
    if (!TRB) {
#pragma unroll
      for (int it = 0; it < BK / bStride; ++it) {
        int r = bRow0 + it * bStride;
        float4 v = *reinterpret_cast<const float4*>(&B[(long long)(k0 + r) * ldb + bCol * 4]);
        *reinterpret_cast<float4*>(&Bs[r][bCol * 4]) = v;
      }
    } else {
#pragma unroll
      for (int it = 0; it < BN / cStride; ++it) {
        int n = cRow0 + it * cStride;
        float4 v = *reinterpret_cast<const float4*>(&B[(long long)n * ldb + k0 + cCol * 4]);
        Bs[cCol * 4 + 0][n] = v.x;
        Bs[cCol * 4 + 1][n] = v.y;
        Bs[cCol * 4 + 2][n] = v.z;
        Bs[cCol * 4 + 3][n] = v.w;
      }
    }
    __syncthreads();

#pragma unroll
    for (int k = 0; k < BK; k++) {
      float a[TM];
#pragma unroll
      for (int i = 0; i < TM; i += 4) {
        float4 v = *reinterpret_cast<const float4*>(&As[k][tRow * TM + i]);
        a[i] = v.x; a[i + 1] = v.y; a[i + 2] = v.z; a[i + 3] = v.w;
      }
      unsigned long long aa[TM];
#pragma unroll
      for (int i = 0; i < TM; i++)
        asm("mov.b64 %0, {%1, %1};" : "=l"(aa[i]) : "f"(a[i]));
      unsigned long long bb[TN / 2];
#pragma unroll
      for (int j = 0; j < TN / 2; j++)
        bb[j] = *reinterpret_cast<const unsigned long long*>(&Bs[k][tCol * TN + 2 * j]);
#pragma unroll
      for (int i = 0; i < TM; i++)
#pragma unroll
        for (int j = 0; j < TN / 2; j++)
          asm("fma.rn.f32x2 %0, %1, %2, %0;" : "+l"(acc[i][j]) : "l"(aa[i]), "l"(bb[j]));
    }
    __syncthreads();
  }

  // epilogue
#pragma unroll
  for (int i = 0; i < TM; i++) {
    int row = tRow * TM + i;
#pragma unroll
    for (int j = 0; j < TN / 2; j++) {
      int col = tCol * TN + 2 * j;
      float2 v = *reinterpret_cast<float2*>(&acc[i][j]);
      float x0 = v.x * alpha, x1 = v.y * alpha;
      if (BIAS) {
        x0 += biasg[(long long)blockIdx.y * BN + col];
        x1 += biasg[(long long)blockIdx.y * BN + col + 1];
      }
      if (RES) {
        float2 r2 = *reinterpret_cast<const float2*>(&R[(long long)row * ldc + col]);
        x0 += r2.x; x1 += r2.y;
      }
      if (RELU) { x0 = fmaxf(x0, 0.f); x1 = fmaxf(x1, 0.f); }
      *reinterpret_cast<float2*>(&C[(long long)row * ldc + col]) = make_float2(x0, x1);
    }
  }
}

// ---------------- Elementwise kernels ----------------
__global__ void embed_k(const int* __restrict__ tok, const float* __restrict__ emb,
                        float* __restrict__ X) {
  int t = blockIdx.x;
  int c4 = threadIdx.x;  // 128 threads, float4 each
  int tk = tok[t];
  float4 v = reinterpret_cast<const float4*>(emb + (long long)tk * DM)[c4];
  v.x *= 8.f; v.y *= 8.f; v.z *= 8.f; v.w *= 8.f;
  reinterpret_cast<float4*>(X + (long long)t * DM)[c4] = v;
}

__global__ void softmax512_k(float* __restrict__ S) {
  int warp = threadIdx.x >> 5, lane = threadIdx.x & 31;
  long long row = (long long)blockIdx.x * 8 + warp;
  float* p = S + row * 512;
  float4 v[4];
  float mx = -1e30f;
#pragma unroll
  for (int it = 0; it < 4; it++) {
    v[it] = *reinterpret_cast<const float4*>(p + it * 128 + lane * 4);
    mx = fmaxf(mx, fmaxf(fmaxf(v[it].x, v[it].y), fmaxf(v[it].z, v[it].w)));
  }
#pragma unroll
  for (int off = 16; off; off >>= 1) mx = fmaxf(mx, __shfl_xor_sync(0xffffffffu, mx, off));
  float sum = 0.f;
#pragma unroll
  for (int it = 0; it < 4; it++) {
    v[it].x = __expf(v[it].x - mx);
    v[it].y = __expf(v[it].y - mx);
    v[it].z = __expf(v[it].z - mx);
    v[it].w = __expf(v[it].w - mx);
    sum += v[it].x + v[it].y + v[it].z + v[it].w;
  }
#pragma unroll
  for (int off = 16; off; off >>= 1) sum += __shfl_xor_sync(0xffffffffu, sum, off);
  float inv = 1.f / sum;
#pragma unroll
  for (int it = 0; it < 4; it++) {
    v[it].x *= inv; v[it].y *= inv; v[it].z *= inv; v[it].w *= inv;
    *reinterpret_cast<float4*>(p + it * 128 + lane * 4) = v[it];
  }
}

__global__ void bn_part_k(const float* __restrict__ Y, float* __restrict__ pS,
                          float* __restrict__ pQ) {
  int c = threadIdx.x;           // 512
  int p = blockIdx.x;            // 256 blocks * 64 rows
  const float* base = Y + (long long)p * 64 * DM + c;
  float s = 0.f, q = 0.f;
#pragma unroll 8
  for (int r = 0; r < 64; r++) {
    float v = base[(long long)r * DM];
    s += v;
    q += v * v;
  }
  pS[p * DM + c] = s;
  pQ[p * DM + c] = q;
}

__global__ void bn_finish_k(const float* __restrict__ pS, const float* __restrict__ pQ,
                            const float* __restrict__ g, const float* __restrict__ be,
                            float* __restrict__ nrm) {
  int c = threadIdx.x;  // 512
  float s = 0.f, q = 0.f;
  for (int p = 0; p < 256; p++) {
    s += pS[p * DM + c];
    q += pQ[p * DM + c];
  }
  const float invN = 1.f / (float)T_TOK;
  float mean = s * invN;
  float var = q * invN - mean * mean;
  float a = g[c] * rsqrtf(var + EPSBN);
  nrm[c] = a;
  nrm[DM + c] = be[c] - mean * a;
}

__global__ void bn_apply_k(const float* __restrict__ Y, const float* __restrict__ nrm,
                           float* __restrict__ X) {
  long long idx = ((long long)blockIdx.x * blockDim.x + threadIdx.x) * 4;
  int c = (int)(idx & (DM - 1));
  float4 v = *reinterpret_cast<const float4*>(Y + idx);
  float4 o;
  o.x = v.x * nrm[c + 0] + nrm[DM + c + 0];
  o.y = v.y * nrm[c + 1] + nrm[DM + c + 1];
  o.z = v.z * nrm[c + 2] + nrm[DM + c + 2];
  o.w = v.w * nrm[c + 3] + nrm[DM + c + 3];
  *reinterpret_cast<float4*>(X + idx) = o;
}

__global__ void copy_k(const float* __restrict__ X, float* __restrict__ out) {
  long long idx = ((long long)blockIdx.x * blockDim.x + threadIdx.x) * 4;
  *reinterpret_cast<float4*>(out + idx) = *reinterpret_cast<const float4*>(X + idx);
}

// ---------------- Host launcher ----------------
extern "C" void kernel_launch(void* const* d_in, const int* in_sizes, int n_in,
                              void* d_out, int out_size) {
  (void)in_sizes; (void)n_in; (void)out_size;
  const int*   tokens = (const int*)d_in[0];
  const float* emb = (const float*)d_in[1];
  const float* WQ  = (const float*)d_in[2];
  const float* WK  = (const float*)d_in[3];
  const float* WV  = (const float*)d_in[4];
  const float* WO  = (const float*)d_in[5];
  const float* g1  = (const float*)d_in[6];
  const float* be1 = (const float*)d_in[7];
  const float* W1  = (const float*)d_in[8];
  const float* b1  = (const float*)d_in[9];
  const float* W2  = (const float*)d_in[10];
  const float* b2  = (const float*)d_in[11];
  const float* g2  = (const float*)d_in[12];
  const float* be2 = (const float*)d_in[13];
  float* out = (float*)d_out;

  void *pX, *pY, *pQ, *pK, *pV, *pATT, *pFFH, *pSC, *ppS, *ppQ, *pnrm;
  cudaGetSymbolAddress(&pX, g_X);
  cudaGetSymbolAddress(&pY, g_Y);
  cudaGetSymbolAddress(&pQ, g_Q);
  cudaGetSymbolAddress(&pK, g_K);
  cudaGetSymbolAddress(&pV, g_V);
  cudaGetSymbolAddress(&pATT, g_ATT);
  cudaGetSymbolAddress(&pFFH, g_FFH);
  cudaGetSymbolAddress(&pSC, g_SC);
  cudaGetSymbolAddress(&ppS, g_partS);
  cudaGetSymbolAddress(&ppQ, g_partQ);
  cudaGetSymbolAddress(&pnrm, g_nrm);
  float *X = (float*)pX, *Y = (float*)pY, *Q = (float*)pQ, *Kb = (float*)pK,
        *V = (float*)pV, *ATT = (float*)pATT, *FFH = (float*)pFFH, *SC = (float*)pSC;
  float *partS = (float*)ppS, *partQ = (float*)ppQ, *nrm = (float*)pnrm;

  const long long TD64 = (long long)T_TOK * DKV;   // per-head Q/K/V stride
  const long long S64 = (long long)SQ * DKV;       // per-batch within head
  const long long SS = (long long)SQ * SQ;

  // Embed
  embed_k<<<T_TOK, 128>>>(tokens, emb, X);

  for (int i = 0; i < NLAYER; i++) {
    const float* wq = WQ + (long long)i * HN * DM * DKV;
    const float* wk = WK + (long long)i * HN * DM * DKV;
    const float* wv = WV + (long long)i * HN * DM * DKV;
    const float* wo = WO + (long long)i * DM * DM;
    const float* w1 = W1 + (long long)i * DM * DFF;
    const float* w2 = W2 + (long long)i * DFF * DM;

    // QKV projections: per-head GEMM  [T,512] @ [512,64]  (batched over h)
    gemm_k<128, 64, 16, 8, 8, false, false, false, false><<<dim3(T_TOK / 128, 1, HN), 128>>>(
        X, wq, Q, nullptr, nullptr, DM, DM, DKV, DKV, 1.f,
        HN, 0, 0, 0, (long long)DM * DKV, 0, TD64);
    gemm_k<128, 64, 16, 8, 8, false, false, false, false><<<dim3(T_TOK / 128, 1, HN), 128>>>(
        X, wk, Kb, nullptr, nullptr, DM, DM, DKV, DKV, 1.f,
        HN, 0, 0, 0, (long long)DM * DKV, 0, TD64);
    gemm_k<128, 64, 16, 8, 8, false, false, false, false><<<dim3(T_TOK / 128, 1, HN), 128>>>(
        X, wv, V, nullptr, nullptr, DM, DM, DKV, DKV, 1.f,
        HN, 0, 0, 0, (long long)DM * DKV, 0, TD64);

    // scores[h,b] = Q[h,b] @ K[h,b]^T / 8   (NT, batched over h*b)
    gemm_k<128, 128, 16, 8, 8, true, false, false, false><<<dim3(4, 4, HN * BATCH), 256>>>(
        Q, Kb, SC, nullptr, nullptr, DKV, DKV, DKV, SQ, 0.125f,
        BATCH, TD64, S64, TD64, S64, (long long)BATCH * SS, SS);

    // softmax over keys
    softmax512_k<<<(HN * BATCH * SQ) / 8, 256>>>(SC);

    // out[h,b] = P @ V[h,b]  -> ATT[t][h*64+v]
    gemm_k<128, 64, 16, 8, 8, false, false, false, false><<<dim3(4, 1, HN * BATCH), 128>>>(
        SC, V, ATT, nullptr, nullptr, SQ, SQ, DKV, DM, 1.f,
        BATCH, (long long)BATCH * SS, SS, TD64, S64, (long long)DKV, (long long)SQ * DM);

    // O projection + residual: Y = X + ATT @ WO
    gemm_k<128, 128, 16, 8, 8, false, false, false, true><<<dim3(T_TOK / 128, 4, 1), 256>>>(
        ATT, wo, Y, X, nullptr, DM, DM, DM, DM, 1.f, 1, 0, 0, 0, 0, 0, 0);

    // BatchNorm1 -> X
    bn_part_k<<<256, DM>>>(Y, partS, partQ);
    bn_finish_k<<<1, DM>>>(partS, partQ, g1 + (long long)i * DM, be1 + (long long)i * DM, nrm);
    bn_apply_k<<<(T_TOK * DM) / 1024, 256>>>(Y, nrm, X);

    // FF1: FFH = relu(X @ W1 + b1)
    gemm_k<128, 128, 16, 8, 8, false, true, true, false><<<dim3(T_TOK / 128, DFF / 128, 1), 256>>>(
        X, w1, FFH, nullptr, b1 + (long long)i * DFF, DM, DM, DFF, DFF, 1.f,
        1, 0, 0, 0, 0, 0, 0);

    // FF2: Y = X + FFH @ W2 + b2
    gemm_k<128, 128, 16, 8, 8, false, true, false, true><<<dim3(T_TOK / 128, 4, 1), 256>>>(
        FFH, w2, Y, X, b2 + (long long)i * DM, DFF, DFF, DM, DM, 1.f,
        1, 0, 0, 0, 0, 0, 0);

    // BatchNorm2 -> X
    bn_part_k<<<256, DM>>>(Y, partS, partQ);
    bn_finish_k<<<1, DM>>>(partS, partQ, g2 + (long long)i * DM, be2 + (long long)i * DM, nrm);
    bn_apply_k<<<(T_TOK * DM) / 1024, 256>>>(Y, nrm, X);
  }

  copy_k<<<(T_TOK * DM) / 1024, 256>>>(X, out);
}

// round 8
// speedup vs baseline: 3.8565x; 2.4187x over previous
#include <cuda_runtime.h>
#include <cuda_bf16.h>
#include <cstdint>

#define T_TOK 16384
#define DM    512
#define DFF   2048
#define HN    8
#define SQ    512
#define BATCH 32
#define NLAYER 6
#define EPSBN 1e-5f
typedef __nv_bfloat16 bf16;
typedef long long ll;

// ---------------- asm helpers (all plain sm_80+ PTX, no arch-specific ops) ----
__device__ __forceinline__ uint32_t smem_u32(const void* p) {
  uint32_t a;
  asm("{ .reg .u64 t; cvta.to.shared.u64 t, %1; cvt.u32.u64 %0, t; }" : "=r"(a) : "l"(p));
  return a;
}
__device__ __forceinline__ void ldsm4(uint32_t* r, uint32_t a) {
  asm volatile("ldmatrix.sync.aligned.m8n8.x4.shared.b16 {%0,%1,%2,%3}, [%4];"
               : "=r"(r[0]), "=r"(r[1]), "=r"(r[2]), "=r"(r[3]) : "r"(a));
}
__device__ __forceinline__ void mma16816(float* c, const uint32_t* a, const uint32_t* b) {
  asm volatile(
      "mma.sync.aligned.m16n8k16.row.col.f32.bf16.bf16.f32 "
      "{%0,%1,%2,%3}, {%4,%5,%6,%7}, {%8,%9}, {%0,%1,%2,%3};"
      : "+f"(c[0]), "+f"(c[1]), "+f"(c[2]), "+f"(c[3])
      : "r"(a[0]), "r"(a[1]), "r"(a[2]), "r"(a[3]), "r"(b[0]), "r"(b[1]));
}
__device__ __forceinline__ void cpa16(uint32_t s, const void* g) {
  asm volatile("cp.async.cg.shared.global [%0], [%1], 16;" :: "r"(s), "l"(g));
}
__device__ __forceinline__ void split2(float v, bf16& h, bf16& l) {
  h = __float2bfloat16(v);
  l = __float2bfloat16(v - __bfloat162float(h));
}
__device__ __forceinline__ uint32_t pack2(bf16 a, bf16 b) {
  return (uint32_t)__bfloat16_as_ushort(a) | ((uint32_t)__bfloat16_as_ushort(b) << 16);
}

// ---------------- Static scratch ----------------
__device__ float g_X[(size_t)T_TOK * DM];
__device__ float g_Y[(size_t)T_TOK * DM];
__device__ float g_SC[(size_t)BATCH * HN * SQ * SQ];
__device__ bf16 g_Xh[(size_t)T_TOK * DM], g_Xl[(size_t)T_TOK * DM];
__device__ bf16 g_QKVh[(size_t)T_TOK * 1536], g_QKVl[(size_t)T_TOK * 1536];
__device__ bf16 g_VTh[(size_t)T_TOK * DM], g_VTl[(size_t)T_TOK * DM];
__device__ bf16 g_Ph[(size_t)BATCH * HN * SQ * SQ], g_Pl[(size_t)BATCH * HN * SQ * SQ];
__device__ bf16 g_ATTh[(size_t)T_TOK * DM], g_ATTl[(size_t)T_TOK * DM];
__device__ bf16 g_Fh[(size_t)T_TOK * DFF], g_Fl[(size_t)T_TOK * DFF];
__device__ bf16 g_WQKVTh[1536 * 512], g_WQKVTl[1536 * 512];
__device__ bf16 g_WOTh[512 * 512],  g_WOTl[512 * 512];
__device__ bf16 g_W1Th[2048 * 512], g_W1Tl[2048 * 512];
__device__ bf16 g_W2Th[512 * 2048], g_W2Tl[512 * 2048];
__device__ float g_partS[256 * DM], g_partQ[256 * DM], g_nrm[2 * DM];

// ---------------- mma.sync bf16x3 GEMM: C = alpha*A@B^T (+bias)(+res)(relu) ----
// A:[M,K] bf16 pairs row-major, B:[N,K] bf16 pairs row-major. M-tile 128, K mult of 32.
// OUTM: 0 -> fp32 C ; 1 -> bf16 pairs (Ch, Cl).
template <int BN, int OUTM, bool BIAS, bool RELU, bool RES>
__global__ void __launch_bounds__(256)
mm_gemm(const bf16* __restrict__ Ah, const bf16* __restrict__ Al,
        const bf16* __restrict__ Bh, const bf16* __restrict__ Bl,
        float* __restrict__ C, bf16* __restrict__ Ch, bf16* __restrict__ Cl,
        const float* __restrict__ Res, const float* __restrict__ bias,
        int K, int lda, int ldb, int ldc, float alpha, int zInner,
        ll sAo, ll sAi, ll sBo, ll sBi, ll sCo, ll sCi) {
  constexpr int WRM = (BN == 128) ? 2 : 4;   // warp grid
  constexpr int WRN = 8 / WRM;
  constexpr int WTM = 128 / WRM;             // 64 or 32
  constexpr int WTN = BN / WRN;              // 32
  constexpr int MT = WTM / 16;               // m-tiles/warp
  constexpr int NT = WTN / 8;                // n-tiles/warp
  constexpr int AB = 128 * 80;               // bytes per A tile (80B padded rows)
  constexpr int BB = BN * 80;
  constexpr int SB = 2 * AB + 2 * BB;        // bytes per stage

  extern __shared__ char dynsm[];
  const uint32_t sb = smem_u32(dynsm);

  const int tid = threadIdx.x, wid = tid >> 5, lane = tid & 31;
  const int wm = wid / WRN, wn = wid % WRN;
  const int zo = blockIdx.z / zInner, zi = blockIdx.z % zInner;

  const bf16* A_h = Ah + zo * sAo + zi * sAi + (ll)blockIdx.x * 128 * lda;
  const bf16* A_l = Al + zo * sAo + zi * sAi + (ll)blockIdx.x * 128 * lda;
  const bf16* B_h = Bh + zo * sBo + zi * sBi + (ll)blockIdx.y * BN * ldb;
  const bf16* B_l = Bl + zo * sBo + zi * sBi + (ll)blockIdx.y * BN * ldb;
  const ll coff = zo * sCo + zi * sCi + (ll)blockIdx.x * 128 * ldc + (ll)blockIdx.y * BN;

  float acc[MT][NT][4];
#pragma unroll
  for (int i = 0; i < MT; i++)
#pragma unroll
    for (int j = 0; j < NT; j++)
#pragma unroll
      for (int e = 0; e < 4; e++) acc[i][j][e] = 0.f;

  auto load_stage = [&](int kt, int s) {
    const int k0 = kt * 32;
    const uint32_t s0 = sb + s * SB;
#pragma unroll 2
    for (int i = tid; i < 128 * 4; i += 256) {
      const int r = i >> 2, c = i & 3;
      const uint32_t so = (uint32_t)(r * 80 + c * 16);
      const ll go = (ll)r * lda + k0 + c * 8;
      cpa16(s0 + so, A_h + go);
      cpa16(s0 + AB + so, A_l + go);
    }
#pragma unroll
    for (int i = tid; i < BN * 4; i += 256) {
      const int r = i >> 2, c = i & 3;
      const uint32_t so = (uint32_t)(r * 80 + c * 16);
      const ll go = (ll)r * ldb + k0 + c * 8;
      cpa16(s0 + 2 * AB + so, B_h + go);
      cpa16(s0 + 2 * AB + BB + so, B_l + go);
    }
  };

  const int KT = K >> 5;
  load_stage(0, 0);
  asm volatile("cp.async.commit_group;");

  const uint32_t arow = (uint32_t)(lane & 15);
  const uint32_t acol = (uint32_t)((lane >> 4) * 16);
  const uint32_t brow = (uint32_t)((lane & 7) + ((lane >> 4) << 3));
  const uint32_t bcol = (uint32_t)(((lane >> 3) & 1) * 16);

  for (int kt = 0; kt < KT; kt++) {
    if (kt + 1 < KT) {
      load_stage(kt + 1, (kt + 1) & 1);
      asm volatile("cp.async.commit_group;");
      asm volatile("cp.async.wait_group 1;");
    } else {
      asm volatile("cp.async.wait_group 0;");
    }
    __syncthreads();

    const uint32_t abase = sb + (kt & 1) * SB;
    const uint32_t bbase = abase + 2 * AB;
#pragma unroll
    for (int ks = 0; ks < 2; ks++) {
      uint32_t aH[MT][4], aL[MT][4], bH[NT][2], bL[NT][2];
#pragma unroll
      for (int mt = 0; mt < MT; mt++) {
        const uint32_t ad = abase + (wm * WTM + mt * 16 + arow) * 80 + ks * 32 + acol;
        ldsm4(aH[mt], ad);
        ldsm4(aL[mt], ad + AB);
      }
#pragma unroll
      for (int p = 0; p < NT / 2; p++) {
        const uint32_t bd = bbase + (wn * WTN + p * 16 + brow) * 80 + ks * 32 + bcol;
        uint32_t t[4];
        ldsm4(t, bd);
        bH[2 * p][0] = t[0]; bH[2 * p][1] = t[1];
        bH[2 * p + 1][0] = t[2]; bH[2 * p + 1][1] = t[3];
        ldsm4(t, bd + BB);
        bL[2 * p][0] = t[0]; bL[2 * p][1] = t[1];
        bL[2 * p + 1][0] = t[2]; bL[2 * p + 1][1] = t[3];
      }
#pragma unroll
      for (int mt = 0; mt < MT; mt++)
#pragma unroll
        for (int nt = 0; nt < NT; nt++) {
          mma16816(acc[mt][nt], aH[mt], bH[nt]);
          mma16816(acc[mt][nt], aH[mt], bL[nt]);
          mma16816(acc[mt][nt], aL[mt], bH[nt]);
        }
    }
    __syncthreads();
  }

  // ---------------- epilogue: registers -> gmem ----------------
#pragma unroll
  for (int mt = 0; mt < MT; mt++) {
#pragma unroll
    for (int nt = 0; nt < NT; nt++) {
      const int r0 = wm * WTM + mt * 16 + (lane >> 2);
      const int cc = wn * WTN + nt * 8 + (lane & 3) * 2;
      float v0 = acc[mt][nt][0] * alpha, v1 = acc[mt][nt][1] * alpha;
      float v2 = acc[mt][nt][2] * alpha, v3 = acc[mt][nt][3] * alpha;
      if (BIAS) {
        const float b0v = bias[(ll)blockIdx.y * BN + cc];
        const float b1v = bias[(ll)blockIdx.y * BN + cc + 1];
        v0 += b0v; v2 += b0v; v1 += b1v; v3 += b1v;
      }
#pragma unroll
      for (int half = 0; half < 2; half++) {
        const int r = r0 + half * 8;
        float x0 = half ? v2 : v0, x1 = half ? v3 : v1;
        const ll go = coff + (ll)r * ldc + cc;
        if (RES) {
          const float2 rr = *reinterpret_cast<const float2*>(Res + go);
          x0 += rr.x; x1 += rr.y;
        }
        if (RELU) { x0 = fmaxf(x0, 0.f); x1 = fmaxf(x1, 0.f); }
        if (OUTM == 0) {
          *reinterpret_cast<float2*>(C + go) = make_float2(x0, x1);
        } else {
          bf16 h0, h1, l0, l1;
          split2(x0, h0, l0); split2(x1, h1, l1);
          *reinterpret_cast<uint32_t*>(Ch + go) = pack2(h0, h1);
          *reinterpret_cast<uint32_t*>(Cl + go) = pack2(l0, l1);
        }
      }
    }
  }
}

// ---------------- transpose + split: fp32 [R,C] -> bf16 pairs [C,R] ----------------
__global__ void tsplit_k(const float* __restrict__ in, bf16* __restrict__ oh,
                         bf16* __restrict__ ol, int R, int C, ll sIn, ll sOut) {
  __shared__ float t[32][33];
  const float* I = in + blockIdx.z * sIn;
  int c0 = blockIdx.x * 32, r0 = blockIdx.y * 32;
#pragma unroll
  for (int i = 0; i < 4; i++)
    t[threadIdx.y + i * 8][threadIdx.x] =
        I[(ll)(r0 + threadIdx.y + i * 8) * C + c0 + threadIdx.x];
  __syncthreads();
#pragma unroll
  for (int i = 0; i < 4; i++) {
    int c = c0 + threadIdx.y + i * 8;
    bf16 h, l;
    split2(t[threadIdx.x][threadIdx.y + i * 8], h, l);
    ll o = blockIdx.z * sOut + (ll)c * R + r0 + threadIdx.x;
    oh[o] = h; ol[o] = l;
  }
}

// ---------------- V transpose: QKV pairs [T,1536] -> VT pairs [(h,b)][64][512] ----
__global__ void vtrans_k(const bf16* __restrict__ ih, const bf16* __restrict__ il,
                         bf16* __restrict__ oh, bf16* __restrict__ ol) {
  __shared__ bf16 th[64][72], tl[64][72];
  int h = blockIdx.x, b = blockIdx.y, s0 = blockIdx.z * 64;
  int tid = threadIdx.x;
  for (int i = tid; i < 64 * 8; i += 256) {
    int row = i >> 3, c8 = i & 7;
    ll gi = (ll)(b * 512 + s0 + row) * 1536 + 1024 + h * 64 + c8 * 8;
    *reinterpret_cast<uint4*>(&th[row][c8 * 8]) = *reinterpret_cast<const uint4*>(ih + gi);
    *reinterpret_cast<uint4*>(&tl[row][c8 * 8]) = *reinterpret_cast<const uint4*>(il + gi);
  }
  __syncthreads();
  for (int i = tid; i < 64 * 64; i += 256) {
    int v = i >> 6, s = i & 63;
    ll o = ((ll)(h * 32 + b) * 64 + v) * 512 + s0 + s;
    oh[o] = th[s][v]; ol[o] = tl[s][v];
  }
}

// ---------------- elementwise ----------------
__global__ void embed_k(const int* __restrict__ tok, const float* __restrict__ emb,
                        float* __restrict__ X, bf16* __restrict__ Xh, bf16* __restrict__ Xl) {
  int t = blockIdx.x, c4 = threadIdx.x;
  float4 v = reinterpret_cast<const float4*>(emb + (ll)tok[t] * DM)[c4];
  v.x *= 8.f; v.y *= 8.f; v.z *= 8.f; v.w *= 8.f;
  ll go = (ll)t * DM + c4 * 4;
  *reinterpret_cast<float4*>(X + go) = v;
  bf16 h0, h1, h2, h3, l0, l1, l2, l3;
  split2(v.x, h0, l0); split2(v.y, h1, l1); split2(v.z, h2, l2); split2(v.w, h3, l3);
  *reinterpret_cast<uint2*>(Xh + go) = make_uint2(pack2(h0, h1), pack2(h2, h3));
  *reinterpret_cast<uint2*>(Xl + go) = make_uint2(pack2(l0, l1), pack2(l2, l3));
}

__global__ void softmax_k(const float* __restrict__ S, bf16* __restrict__ Ph,
                          bf16* __restrict__ Pl) {
  int warp = threadIdx.x >> 5, lane = threadIdx.x & 31;
  ll row = (ll)blockIdx.x * 8 + warp;
  const float* p = S + row * 512;
  float4 v[4];
  float mx = -1e30f;
#pragma unroll
  for (int it = 0; it < 4; it++) {
    v[it] = *reinterpret_cast<const float4*>(p + it * 128 + lane * 4);
    mx = fmaxf(mx, fmaxf(fmaxf(v[it].x, v[it].y), fmaxf(v[it].z, v[it].w)));
  }
#pragma unroll
  for (int o = 16; o; o >>= 1) mx = fmaxf(mx, __shfl_xor_sync(0xffffffffu, mx, o));
  float sum = 0.f;
#pragma unroll
  for (int it = 0; it < 4; it++) {
    v[it].x = __expf(v[it].x - mx); v[it].y = __expf(v[it].y - mx);
    v[it].z = __expf(v[it].z - mx); v[it].w = __expf(v[it].w - mx);
    sum += v[it].x + v[it].y + v[it].z + v[it].w;
  }
#pragma unroll
  for (int o = 16; o; o >>= 1) sum += __shfl_xor_sync(0xffffffffu, sum, o);
  float inv = 1.f / sum;
#pragma unroll
  for (int it = 0; it < 4; it++) {
    float x0 = v[it].x * inv, x1 = v[it].y * inv, x2 = v[it].z * inv, x3 = v[it].w * inv;
    bf16 h0, h1, h2, h3, l0, l1, l2, l3;
    split2(x0, h0, l0); split2(x1, h1, l1); split2(x2, h2, l2); split2(x3, h3, l3);
    ll go = row * 512 + it * 128 + lane * 4;
    *reinterpret_cast<uint2*>(Ph + go) = make_uint2(pack2(h0, h1), pack2(h2, h3));
    *reinterpret_cast<uint2*>(Pl + go) = make_uint2(pack2(l0, l1), pack2(l2, l3));
  }
}

__global__ void bn_part_k(const float* __restrict__ Y, float* __restrict__ pS,
                          float* __restrict__ pQ) {
  int c = threadIdx.x, p = blockIdx.x;
  const float* base = Y + (ll)p * 64 * DM + c;
  float s = 0.f, q = 0.f;
#pragma unroll 8
  for (int r = 0; r < 64; r++) { float v = base[(ll)r * DM]; s += v; q += v * v; }
  pS[p * DM + c] = s; pQ[p * DM + c] = q;
}
__global__ void bn_finish_k(const float* __restrict__ pS, const float* __restrict__ pQ,
                            const float* __restrict__ g, const float* __restrict__ be,
                            float* __restrict__ nrm) {
  int c = threadIdx.x;
  float s = 0.f, q = 0.f;
  for (int p = 0; p < 256; p++) { s += pS[p * DM + c]; q += pQ[p * DM + c]; }
  const float invN = 1.f / (float)T_TOK;
  float mean = s * invN, var = q * invN - mean * mean;
  float a = g[c] * rsqrtf(var + EPSBN);
  nrm[c] = a; nrm[DM + c] = be[c] - mean * a;
}
__global__ void bn_apply_k(const float* __restrict__ Y, const float* __restrict__ nrm,
                           float* __restrict__ X, bf16* __restrict__ Xh, bf16* __restrict__ Xl) {
  ll idx = ((ll)blockIdx.x * blockDim.x + threadIdx.x) * 4;
  int c = (int)(idx & (DM - 1));
  float4 v = *reinterpret_cast<const float4*>(Y + idx);
  float4 o;
  o.x = v.x * nrm[c] + nrm[DM + c];
  o.y = v.y * nrm[c + 1] + nrm[DM + c + 1];
  o.z = v.z * nrm[c + 2] + nrm[DM + c + 2];
  o.w = v.w * nrm[c + 3] + nrm[DM + c + 3];
  *reinterpret_cast<float4*>(X + idx) = o;
  bf16 h0, h1, h2, h3, l0, l1, l2, l3;
  split2(o.x, h0, l0); split2(o.y, h1, l1); split2(o.z, h2, l2); split2(o.w, h3, l3);
  *reinterpret_cast<uint2*>(Xh + idx) = make_uint2(pack2(h0, h1), pack2(h2, h3));
  *reinterpret_cast<uint2*>(Xl + idx) = make_uint2(pack2(l0, l1), pack2(l2, l3));
}
__global__ void copy_k(const float* __restrict__ X, float* __restrict__ out) {
  ll idx = ((ll)blockIdx.x * blockDim.x + threadIdx.x) * 4;
  *reinterpret_cast<float4*>(out + idx) = *reinterpret_cast<const float4*>(X + idx);
}

// ---------------- host ----------------
#define GETP(var, sym) void* p_##var; cudaGetSymbolAddress(&p_##var, sym)
extern "C" void kernel_launch(void* const* d_in, const int* in_sizes, int n_in,
                              void* d_out, int out_size) {
  (void)in_sizes; (void)n_in; (void)out_size;
  const int* tokens = (const int*)d_in[0];
  const float* emb = (const float*)d_in[1];
  const float *WQ = (const float*)d_in[2], *WK = (const float*)d_in[3];
  const float *WV = (const float*)d_in[4], *WO = (const float*)d_in[5];
  const float *g1 = (const float*)d_in[6], *be1 = (const float*)d_in[7];
  const float *W1 = (const float*)d_in[8], *b1 = (const float*)d_in[9];
  const float *W2 = (const float*)d_in[10], *b2 = (const float*)d_in[11];
  const float *g2 = (const float*)d_in[12], *be2 = (const float*)d_in[13];
  float* out = (float*)d_out;

  GETP(X, g_X); GETP(Y, g_Y); GETP(SC, g_SC);
  GETP(Xh, g_Xh); GETP(Xl, g_Xl); GETP(QKVh, g_QKVh); GETP(QKVl, g_QKVl);
  GETP(VTh, g_VTh); GETP(VTl, g_VTl); GETP(Ph, g_Ph); GETP(Pl, g_Pl);
  GETP(ATTh, g_ATTh); GETP(ATTl, g_ATTl); GETP(Fh, g_Fh); GETP(Fl, g_Fl);
  GETP(WQKVTh, g_WQKVTh); GETP(WQKVTl, g_WQKVTl); GETP(WOTh, g_WOTh); GETP(WOTl, g_WOTl);
  GETP(W1Th, g_W1Th); GETP(W1Tl, g_W1Tl); GETP(W2Th, g_W2Th); GETP(W2Tl, g_W2Tl);
  GETP(pS, g_partS); GETP(pQ, g_partQ); GETP(nrm, g_nrm);
  float *X = (float*)p_X, *Y = (float*)p_Y, *SC = (float*)p_SC;
  bf16 *Xh = (bf16*)p_Xh, *Xl = (bf16*)p_Xl, *QKVh = (bf16*)p_QKVh, *QKVl = (bf16*)p_QKVl;
  bf16 *VTh = (bf16*)p_VTh, *VTl = (bf16*)p_VTl, *Ph = (bf16*)p_Ph, *Pl = (bf16*)p_Pl;
  bf16 *ATTh = (bf16*)p_ATTh, *ATTl = (bf16*)p_ATTl, *Fh = (bf16*)p_Fh, *Fl = (bf16*)p_Fl;
  bf16 *WQKVTh = (bf16*)p_WQKVTh, *WQKVTl = (bf16*)p_WQKVTl;
  bf16 *WOTh = (bf16*)p_WOTh, *WOTl = (bf16*)p_WOTl;
  bf16 *W1Th = (bf16*)p_W1Th, *W1Tl = (bf16*)p_W1Tl;
  bf16 *W2Th = (bf16*)p_W2Th, *W2Tl = (bf16*)p_W2Tl;
  float *partS = (float*)p_pS, *partQ = (float*)p_pQ, *nrm = (float*)p_nrm;

  // stage bytes: 2*(128*80) + 2*(BN*80); double buffered
  const int SM128 = 2 * (2 * 128 * 80 + 2 * 128 * 80);  // 81920
  const int SM64  = 2 * (2 * 128 * 80 + 2 * 64 * 80);   // 61440
  cudaFuncSetAttribute(mm_gemm<128, 1, false, false, false>, cudaFuncAttributeMaxDynamicSharedMemorySize, SM128);
  cudaFuncSetAttribute(mm_gemm<128, 0, false, false, false>, cudaFuncAttributeMaxDynamicSharedMemorySize, SM128);
  cudaFuncSetAttribute(mm_gemm<64, 1, false, false, false>,  cudaFuncAttributeMaxDynamicSharedMemorySize, SM64);
  cudaFuncSetAttribute(mm_gemm<128, 0, false, false, true>,  cudaFuncAttributeMaxDynamicSharedMemorySize, SM128);
  cudaFuncSetAttribute(mm_gemm<128, 1, true, true, false>,   cudaFuncAttributeMaxDynamicSharedMemorySize, SM128);
  cudaFuncSetAttribute(mm_gemm<128, 0, true, false, true>,   cudaFuncAttributeMaxDynamicSharedMemorySize, SM128);

  const ll SS = (ll)SQ * SQ;
  dim3 tb32(32, 8);

  embed_k<<<T_TOK, 128>>>(tokens, emb, X, Xh, Xl);

  for (int i = 0; i < NLAYER; i++) {
    const float* wq = WQ + (ll)i * HN * DM * 64;
    const float* wk = WK + (ll)i * HN * DM * 64;
    const float* wv = WV + (ll)i * HN * DM * 64;
    const float* wo = WO + (ll)i * DM * DM;
    const float* w1 = W1 + (ll)i * DM * DFF;
    const float* w2 = W2 + (ll)i * DFF * DM;

    tsplit_k<<<dim3(2, 16, 8), tb32>>>(wq, WQKVTh, WQKVTl, 512, 64, 512 * 64, 64 * 512);
    tsplit_k<<<dim3(2, 16, 8), tb32>>>(wk, WQKVTh + 512 * 512, WQKVTl + 512 * 512, 512, 64, 512 * 64, 64 * 512);
    tsplit_k<<<dim3(2, 16, 8), tb32>>>(wv, WQKVTh + 1024 * 512, WQKVTl + 1024 * 512, 512, 64, 512 * 64, 64 * 512);
    tsplit_k<<<dim3(16, 16, 1), tb32>>>(wo, WOTh, WOTl, 512, 512, 0, 0);
    tsplit_k<<<dim3(64, 16, 1), tb32>>>(w1, W1Th, W1Tl, 512, 2048, 0, 0);
    tsplit_k<<<dim3(16, 64, 1), tb32>>>(w2, W2Th, W2Tl, 2048, 512, 0, 0);

    // QKV: [T,512] @ [1536,512]^T -> pairs [T,1536]
    mm_gemm<128, 1, false, false, false><<<dim3(128, 12, 1), 256, SM128>>>(
        Xh, Xl, WQKVTh, WQKVTl, nullptr, QKVh, QKVl, nullptr, nullptr,
        512, 512, 512, 1536, 1.f, 1, 0, 0, 0, 0, 0, 0);

    vtrans_k<<<dim3(8, 32, 8), 256>>>(QKVh, QKVl, VTh, VTl);

    // scores: per (h,b) Q@K^T/8 -> SC fp32
    mm_gemm<128, 0, false, false, false><<<dim3(4, 4, 256), 256, SM128>>>(
        QKVh, QKVl, QKVh + 512, QKVl + 512, SC, nullptr, nullptr, nullptr, nullptr,
        64, 1536, 1536, 512, 0.125f, 32,
        64, (ll)512 * 1536, 64, (ll)512 * 1536, 32 * SS, SS);

    softmax_k<<<HN * BATCH * SQ / 8, 256>>>(SC, Ph, Pl);

    // AV: per (h,b) P@VT^T -> ATT pairs [t][h*64+v]
    mm_gemm<64, 1, false, false, false><<<dim3(4, 1, 256), 256, SM64>>>(
        Ph, Pl, VTh, VTl, nullptr, ATTh, ATTl, nullptr, nullptr,
        512, 512, 512, 512, 1.f, 32,
        32 * SS, SS, (ll)32 * 64 * 512, 64 * 512, 64, (ll)512 * 512);

    // O-proj + residual -> Y fp32
    mm_gemm<128, 0, false, false, true><<<dim3(128, 4, 1), 256, SM128>>>(
        ATTh, ATTl, WOTh, WOTl, Y, nullptr, nullptr, X, nullptr,
        512, 512, 512, 512, 1.f, 1, 0, 0, 0, 0, 0, 0);

    bn_part_k<<<256, DM>>>(Y, partS, partQ);
    bn_finish_k<<<1, DM>>>(partS, partQ, g1 + (ll)i * DM, be1 + (ll)i * DM, nrm);
    bn_apply_k<<<T_TOK * DM / 1024, 256>>>(Y, nrm, X, Xh, Xl);

    // FF1: relu(X@W1+b1) -> pairs
    mm_gemm<128, 1, true, true, false><<<dim3(128, 16, 1), 256, SM128>>>(
        Xh, Xl, W1Th, W1Tl, nullptr, Fh, Fl, nullptr, b1 + (ll)i * DFF,
        512, 512, 512, 2048, 1.f, 1, 0, 0, 0, 0, 0, 0);

    // FF2 + bias + residual -> Y fp32
    mm_gemm<128, 0, true, false, true><<<dim3(128, 4, 1), 256, SM128>>>(
        Fh, Fl, W2Th, W2Tl, Y, nullptr, nullptr, X, b2 + (ll)i * DM,
        2048, 2048, 2048, 512, 1.f, 1, 0, 0, 0, 0, 0, 0);

    bn_part_k<<<256, DM>>>(Y, partS, partQ);
    bn_finish_k<<<1, DM>>>(partS, partQ, g2 + (ll)i * DM, be2 + (ll)i * DM, nrm);
    bn_apply_k<<<T_TOK * DM / 1024, 256>>>(Y, nrm, X, Xh, Xl);
  }

  copy_k<<<T_TOK * DM / 1024, 256>>>(X, out);
}

// round 9
// speedup vs baseline: 4.8840x; 1.2664x over previous
#include <cuda_runtime.h>
#include <cuda_fp16.h>
#include <cstdint>

#define T_TOK 16384
#define DM    512
#define DFF   2048
#define HN    8
#define SQ    512
#define BATCH 32
#define NLAYER 6
#define EPSBN 1e-5f
typedef __half h16;
typedef long long ll;

// ---------------- asm helpers (plain sm_80+ PTX) ----------------
__device__ __forceinline__ uint32_t smem_u32(const void* p) {
  uint32_t a;
  asm("{ .reg .u64 t; cvta.to.shared.u64 t, %1; cvt.u32.u64 %0, t; }" : "=r"(a) : "l"(p));
  return a;
}
__device__ __forceinline__ void ldsm4(uint32_t* r, uint32_t a) {
  asm volatile("ldmatrix.sync.aligned.m8n8.x4.shared.b16 {%0,%1,%2,%3}, [%4];"
               : "=r"(r[0]), "=r"(r[1]), "=r"(r[2]), "=r"(r[3]) : "r"(a));
}
__device__ __forceinline__ void mma16816(float* c, const uint32_t* a, const uint32_t* b) {
  asm volatile(
      "mma.sync.aligned.m16n8k16.row.col.f32.f16.f16.f32 "
      "{%0,%1,%2,%3}, {%4,%5,%6,%7}, {%8,%9}, {%0,%1,%2,%3};"
      : "+f"(c[0]), "+f"(c[1]), "+f"(c[2]), "+f"(c[3])
      : "r"(a[0]), "r"(a[1]), "r"(a[2]), "r"(a[3]), "r"(b[0]), "r"(b[1]));
}
__device__ __forceinline__ void cpa16(uint32_t s, const void* g) {
  asm volatile("cp.async.cg.shared.global [%0], [%1], 16;" :: "r"(s), "l"(g));
}
__device__ __forceinline__ void split2(float v, h16& h, h16& l) {
  h = __float2half_rn(v);
  l = __float2half_rn(v - __half2float(h));
}
__device__ __forceinline__ uint32_t pack2(h16 a, h16 b) {
  return (uint32_t)__half_as_ushort(a) | ((uint32_t)__half_as_ushort(b) << 16);
}

// ---------------- Static scratch ----------------
__device__ float g_X[(size_t)T_TOK * DM];
__device__ float g_Y[(size_t)T_TOK * DM];
__device__ float g_SC[(size_t)BATCH * HN * SQ * SQ];
__device__ h16 g_Xh[(size_t)T_TOK * DM], g_Xl[(size_t)T_TOK * DM];
__device__ h16 g_QKVh[(size_t)T_TOK * 1536], g_QKVl[(size_t)T_TOK * 1536];
__device__ h16 g_VTh[(size_t)T_TOK * DM];
__device__ h16 g_Ph[(size_t)BATCH * HN * SQ * SQ], g_Pl[(size_t)BATCH * HN * SQ * SQ];
__device__ h16 g_ATTh[(size_t)T_TOK * DM], g_ATTl[(size_t)T_TOK * DM];
__device__ h16 g_Fh[(size_t)T_TOK * DFF], g_Fl[(size_t)T_TOK * DFF];
__device__ h16 g_WQKVTh[1536 * 512];
__device__ h16 g_WOTh[512 * 512];
__device__ h16 g_W1Th[2048 * 512];
__device__ h16 g_W2Th[512 * 2048];
__device__ float g_partS[256 * DM], g_partQ[256 * DM], g_nrm[2 * DM];

// ------- mma.sync fp16 2-MMA GEMM: C = alpha*(Ah+Al)@Bh^T (+bias)(+res)(relu) -------
// A:[M,K] fp16 hi/lo pair row-major; B:[N,K] fp16 hi row-major. M-tile 128, K mult 32.
// OUTM: 0 -> fp32 C ; 1 -> fp16 pair (Ch, Cl).
template <int BN, int OUTM, bool BIAS, bool RELU, bool RES>
__global__ void __launch_bounds__(256)
mm_gemm(const h16* __restrict__ Ah, const h16* __restrict__ Al,
        const h16* __restrict__ Bh,
        float* __restrict__ C, h16* __restrict__ Ch, h16* __restrict__ Cl,
        const float* __restrict__ Res, const float* __restrict__ bias,
        int K, int lda, int ldb, int ldc, float alpha, int zInner,
        ll sAo, ll sAi, ll sBo, ll sBi, ll sCo, ll sCi) {
  constexpr int WRM = (BN == 128) ? 2 : 4;
  constexpr int WRN = 8 / WRM;
  constexpr int WTM = 128 / WRM;
  constexpr int WTN = BN / WRN;
  constexpr int MT = WTM / 16;
  constexpr int NT = WTN / 8;
  constexpr int AB = 128 * 80;           // one A tile (80B padded rows)
  constexpr int BB = BN * 80;
  constexpr int SB = 2 * AB + BB;        // stage bytes: Ah + Al + Bh

  extern __shared__ char dynsm[];
  const uint32_t sb = smem_u32(dynsm);

  const int tid = threadIdx.x, wid = tid >> 5, lane = tid & 31;
  const int wm = wid / WRN, wn = wid % WRN;
  const int zo = blockIdx.z / zInner, zi = blockIdx.z % zInner;

  const h16* A_h = Ah + zo * sAo + zi * sAi + (ll)blockIdx.x * 128 * lda;
  const h16* A_l = Al + zo * sAo + zi * sAi + (ll)blockIdx.x * 128 * lda;
  const h16* B_h = Bh + zo * sBo + zi * sBi + (ll)blockIdx.y * BN * ldb;
  const ll coff = zo * sCo + zi * sCi + (ll)blockIdx.x * 128 * ldc + (ll)blockIdx.y * BN;

  float acc[MT][NT][4];
#pragma unroll
  for (int i = 0; i < MT; i++)
#pragma unroll
    for (int j = 0; j < NT; j++)
#pragma unroll
      for (int e = 0; e < 4; e++) acc[i][j][e] = 0.f;

  auto load_stage = [&](int kt, int s) {
    const int k0 = kt * 32;
    const uint32_t s0 = sb + s * SB;
#pragma unroll 2
    for (int i = tid; i < 128 * 4; i += 256) {
      const int r = i >> 2, c = i & 3;
      const uint32_t so = (uint32_t)(r * 80 + c * 16);
      const ll go = (ll)r * lda + k0 + c * 8;
      cpa16(s0 + so, A_h + go);
      cpa16(s0 + AB + so, A_l + go);
    }
#pragma unroll
    for (int i = tid; i < BN * 4; i += 256) {
      const int r = i >> 2, c = i & 3;
      cpa16(s0 + 2 * AB + (uint32_t)(r * 80 + c * 16), B_h + (ll)r * ldb + k0 + c * 8);
    }
  };

  const int KT = K >> 5;
  load_stage(0, 0);
  asm volatile("cp.async.commit_group;");

  const uint32_t arow = (uint32_t)(lane & 15);
  const uint32_t acol = (uint32_t)((lane >> 4) * 16);
  const uint32_t brow = (uint32_t)((lane & 7) + ((lane >> 4) << 3));
  const uint32_t bcol = (uint32_t)(((lane >> 3) & 1) * 16);

  for (int kt = 0; kt < KT; kt++) {
    if (kt + 1 < KT) {
      load_stage(kt + 1, (kt + 1) & 1);
      asm volatile("cp.async.commit_group;");
      asm volatile("cp.async.wait_group 1;");
    } else {
      asm volatile("cp.async.wait_group 0;");
    }
    __syncthreads();

    const uint32_t abase = sb + (kt & 1) * SB;
    const uint32_t bbase = abase + 2 * AB;
#pragma unroll
    for (int ks = 0; ks < 2; ks++) {
      uint32_t aH[MT][4], aL[MT][4], bH[NT][2];
#pragma unroll
      for (int mt = 0; mt < MT; mt++) {
        const uint32_t ad = abase + (wm * WTM + mt * 16 + arow) * 80 + ks * 32 + acol;
        ldsm4(aH[mt], ad);
        ldsm4(aL[mt], ad + AB);
      }
#pragma unroll
      for (int p = 0; p < NT / 2; p++) {
        const uint32_t bd = bbase + (wn * WTN + p * 16 + brow) * 80 + ks * 32 + bcol;
        uint32_t t[4];
        ldsm4(t, bd);
        bH[2 * p][0] = t[0]; bH[2 * p][1] = t[1];
        bH[2 * p + 1][0] = t[2]; bH[2 * p + 1][1] = t[3];
      }
#pragma unroll
      for (int mt = 0; mt < MT; mt++)
#pragma unroll
        for (int nt = 0; nt < NT; nt++) {
          mma16816(acc[mt][nt], aH[mt], bH[nt]);
          mma16816(acc[mt][nt], aL[mt], bH[nt]);
        }
    }
    __syncthreads();
  }

  // ---------------- epilogue ----------------
#pragma unroll
  for (int mt = 0; mt < MT; mt++) {
#pragma unroll
    for (int nt = 0; nt < NT; nt++) {
      const int r0 = wm * WTM + mt * 16 + (lane >> 2);
      const int cc = wn * WTN + nt * 8 + (lane & 3) * 2;
      float v0 = acc[mt][nt][0] * alpha, v1 = acc[mt][nt][1] * alpha;
      float v2 = acc[mt][nt][2] * alpha, v3 = acc[mt][nt][3] * alpha;
      if (BIAS) {
        const float b0v = bias[(ll)blockIdx.y * BN + cc];
        const float b1v = bias[(ll)blockIdx.y * BN + cc + 1];
        v0 += b0v; v2 += b0v; v1 += b1v; v3 += b1v;
      }
#pragma unroll
      for (int half = 0; half < 2; half++) {
        const int r = r0 + half * 8;
        float x0 = half ? v2 : v0, x1 = half ? v3 : v1;
        const ll go = coff + (ll)r * ldc + cc;
        if (RES) {
          const float2 rr = *reinterpret_cast<const float2*>(Res + go);
          x0 += rr.x; x1 += rr.y;
        }
        if (RELU) { x0 = fmaxf(x0, 0.f); x1 = fmaxf(x1, 0.f); }
        if (OUTM == 0) {
          *reinterpret_cast<float2*>(C + go) = make_float2(x0, x1);
        } else {
          h16 h0, h1, l0, l1;
          split2(x0, h0, l0); split2(x1, h1, l1);
          *reinterpret_cast<uint32_t*>(Ch + go) = pack2(h0, h1);
          *reinterpret_cast<uint32_t*>(Cl + go) = pack2(l0, l1);
        }
      }
    }
  }
}

// -------- transpose + round: fp32 [R,C] -> fp16 hi [C,R] --------
__global__ void tsplit_k(const float* __restrict__ in, h16* __restrict__ oh,
                         int R, int C, ll sIn, ll sOut) {
  __shared__ float t[32][33];
  const float* I = in + blockIdx.z * sIn;
  int c0 = blockIdx.x * 32, r0 = blockIdx.y * 32;
#pragma unroll
  for (int i = 0; i < 4; i++)
    t[threadIdx.y + i * 8][threadIdx.x] =
        I[(ll)(r0 + threadIdx.y + i * 8) * C + c0 + threadIdx.x];
  __syncthreads();
#pragma unroll
  for (int i = 0; i < 4; i++) {
    int c = c0 + threadIdx.y + i * 8;
    ll o = blockIdx.z * sOut + (ll)c * R + r0 + threadIdx.x;
    oh[o] = __float2half_rn(t[threadIdx.x][threadIdx.y + i * 8]);
  }
}

// -------- V transpose: QKV hi [T,1536] -> VT hi [(h,b)][64][512] --------
__global__ void vtrans_k(const h16* __restrict__ ih, h16* __restrict__ oh) {
  __shared__ h16 th[64][72];
  int h = blockIdx.x, b = blockIdx.y, s0 = blockIdx.z * 64;
  int tid = threadIdx.x;
  for (int i = tid; i < 64 * 8; i += 256) {
    int row = i >> 3, c8 = i & 7;
    ll gi = (ll)(b * 512 + s0 + row) * 1536 + 1024 + h * 64 + c8 * 8;
    *reinterpret_cast<uint4*>(&th[row][c8 * 8]) = *reinterpret_cast<const uint4*>(ih + gi);
  }
  __syncthreads();
  for (int i = tid; i < 64 * 64; i += 256) {
    int v = i >> 6, s = i & 63;
    oh[((ll)(h * 32 + b) * 64 + v) * 512 + s0 + s] = th[s][v];
  }
}

// ---------------- elementwise ----------------
__global__ void embed_k(const int* __restrict__ tok, const float* __restrict__ emb,
                        float* __restrict__ X, h16* __restrict__ Xh, h16* __restrict__ Xl) {
  int t = blockIdx.x, c4 = threadIdx.x;
  float4 v = reinterpret_cast<const float4*>(emb + (ll)tok[t] * DM)[c4];
  v.x *= 8.f; v.y *= 8.f; v.z *= 8.f; v.w *= 8.f;
  ll go = (ll)t * DM + c4 * 4;
  *reinterpret_cast<float4*>(X + go) = v;
  h16 h0, h1, h2, h3, l0, l1, l2, l3;
  split2(v.x, h0, l0); split2(v.y, h1, l1); split2(v.z, h2, l2); split2(v.w, h3, l3);
  *reinterpret_cast<uint2*>(Xh + go) = make_uint2(pack2(h0, h1), pack2(h2, h3));
  *reinterpret_cast<uint2*>(Xl + go) = make_uint2(pack2(l0, l1), pack2(l2, l3));
}

__global__ void softmax_k(const float* __restrict__ S, h16* __restrict__ Ph,
                          h16* __restrict__ Pl) {
  int warp = threadIdx.x >> 5, lane = threadIdx.x & 31;
  ll row = (ll)blockIdx.x * 8 + warp;
  const float* p = S + row * 512;
  float4 v[4];
  float mx = -1e30f;
#pragma unroll
  for (int it = 0; it < 4; it++) {
    v[it] = *reinterpret_cast<const float4*>(p + it * 128 + lane * 4);
    mx = fmaxf(mx, fmaxf(fmaxf(v[it].x, v[it].y), fmaxf(v[it].z, v[it].w)));
  }
#pragma unroll
  for (int o = 16; o; o >>= 1) mx = fmaxf(mx, __shfl_xor_sync(0xffffffffu, mx, o));
  float sum = 0.f;
#pragma unroll
  for (int it = 0; it < 4; it++) {
    v[it].x = __expf(v[it].x - mx); v[it].y = __expf(v[it].y - mx);
    v[it].z = __expf(v[it].z - mx); v[it].w = __expf(v[it].w - mx);
    sum += v[it].x + v[it].y + v[it].z + v[it].w;
  }
#pragma unroll
  for (int o = 16; o; o >>= 1) sum += __shfl_xor_sync(0xffffffffu, sum, o);
  float inv = 1.f / sum;
#pragma unroll
  for (int it = 0; it < 4; it++) {
    float x0 = v[it].x * inv, x1 = v[it].y * inv, x2 = v[it].z * inv, x3 = v[it].w * inv;
    h16 h0, h1, h2, h3, l0, l1, l2, l3;
    split2(x0, h0, l0); split2(x1, h1, l1); split2(x2, h2, l2); split2(x3, h3, l3);
    ll go = row * 512 + it * 128 + lane * 4;
    *reinterpret_cast<uint2*>(Ph + go) = make_uint2(pack2(h0, h1), pack2(h2, h3));
    *reinterpret_cast<uint2*>(Pl + go) = make_uint2(pack2(l0, l1), pack2(l2, l3));
  }
}

__global__ void bn_part_k(const float* __restrict__ Y, float* __restrict__ pS,
                          float* __restrict__ pQ) {
  int c = threadIdx.x, p = blockIdx.x;
  const float* base = Y + (ll)p * 64 * DM + c;
  float s = 0.f, q = 0.f;
#pragma unroll 8
  for (int r = 0; r < 64; r++) { float v = base[(ll)r * DM]; s += v; q += v * v; }
  pS[p * DM + c] = s; pQ[p * DM + c] = q;
}
__global__ void bn_finish_k(const float* __restrict__ pS, const float* __restrict__ pQ,
                            const float* __restrict__ g, const float* __restrict__ be,
                            float* __restrict__ nrm) {
  int c = threadIdx.x;
  float s = 0.f, q = 0.f;
  for (int p = 0; p < 256; p++) { s += pS[p * DM + c]; q += pQ[p * DM + c]; }
  const float invN = 1.f / (float)T_TOK;
  float mean = s * invN, var = q * invN - mean * mean;
  float a = g[c] * rsqrtf(var + EPSBN);
  nrm[c] = a; nrm[DM + c] = be[c] - mean * a;
}
__global__ void bn_apply_k(const float* __restrict__ Y, const float* __restrict__ nrm,
                           float* __restrict__ X, h16* __restrict__ Xh, h16* __restrict__ Xl) {
  ll idx = ((ll)blockIdx.x * blockDim.x + threadIdx.x) * 4;
  int c = (int)(idx & (DM - 1));
  float4 v = *reinterpret_cast<const float4*>(Y + idx);
  float4 o;
  o.x = v.x * nrm[c] + nrm[DM + c];
  o.y = v.y * nrm[c + 1] + nrm[DM + c + 1];
  o.z = v.z * nrm[c + 2] + nrm[DM + c + 2];
  o.w = v.w * nrm[c + 3] + nrm[DM + c + 3];
  *reinterpret_cast<float4*>(X + idx) = o;
  h16 h0, h1, h2, h3, l0, l1, l2, l3;
  split2(o.x, h0, l0); split2(o.y, h1, l1); split2(o.z, h2, l2); split2(o.w, h3, l3);
  *reinterpret_cast<uint2*>(Xh + idx) = make_uint2(pack2(h0, h1), pack2(h2, h3));
  *reinterpret_cast<uint2*>(Xl + idx) = make_uint2(pack2(l0, l1), pack2(l2, l3));
}
__global__ void copy_k(const float* __restrict__ X, float* __restrict__ out) {
  ll idx = ((ll)blockIdx.x * blockDim.x + threadIdx.x) * 4;
  *reinterpret_cast<float4*>(out + idx) = *reinterpret_cast<const float4*>(X + idx);
}

// ---------------- host ----------------
#define GETP(var, sym) void* p_##var; cudaGetSymbolAddress(&p_##var, sym)
extern "C" void kernel_launch(void* const* d_in, const int* in_sizes, int n_in,
                              void* d_out, int out_size) {
  (void)in_sizes; (void)n_in; (void)out_size;
  const int* tokens = (const int*)d_in[0];
  const float* emb = (const float*)d_in[1];
  const float *WQ = (const float*)d_in[2], *WK = (const float*)d_in[3];
  const float *WV = (const float*)d_in[4], *WO = (const float*)d_in[5];
  const float *g1 = (const float*)d_in[6], *be1 = (const float*)d_in[7];
  const float *W1 = (const float*)d_in[8], *b1 = (const float*)d_in[9];
  const float *W2 = (const float*)d_in[10], *b2 = (const float*)d_in[11];
  const float *g2 = (const float*)d_in[12], *be2 = (const float*)d_in[13];
  float* out = (float*)d_out;

  GETP(X, g_X); GETP(Y, g_Y); GETP(SC, g_SC);
  GETP(Xh, g_Xh); GETP(Xl, g_Xl); GETP(QKVh, g_QKVh); GETP(QKVl, g_QKVl);
  GETP(VTh, g_VTh); GETP(Ph, g_Ph); GETP(Pl, g_Pl);
  GETP(ATTh, g_ATTh); GETP(ATTl, g_ATTl); GETP(Fh, g_Fh); GETP(Fl, g_Fl);
  GETP(WQKVTh, g_WQKVTh); GETP(WOTh, g_WOTh);
  GETP(W1Th, g_W1Th); GETP(W2Th, g_W2Th);
  GETP(pS, g_partS); GETP(pQ, g_partQ); GETP(nrm, g_nrm);
  float *X = (float*)p_X, *Y = (float*)p_Y, *SC = (float*)p_SC;
  h16 *Xh = (h16*)p_Xh, *Xl = (h16*)p_Xl, *QKVh = (h16*)p_QKVh, *QKVl = (h16*)p_QKVl;
  h16 *VTh = (h16*)p_VTh, *Ph = (h16*)p_Ph, *Pl = (h16*)p_Pl;
  h16 *ATTh = (h16*)p_ATTh, *ATTl = (h16*)p_ATTl, *Fh = (h16*)p_Fh, *Fl = (h16*)p_Fl;
  h16 *WQKVTh = (h16*)p_WQKVTh, *WOTh = (h16*)p_WOTh;
  h16 *W1Th = (h16*)p_W1Th, *W2Th = (h16*)p_W2Th;
  float *partS = (float*)p_pS, *partQ = (float*)p_pQ, *nrm = (float*)p_nrm;

  // stage bytes: 2*(128*80) + BN*80, double buffered
  const int SM128 = 2 * (2 * 128 * 80 + 128 * 80);  // 61440
  const int SM64  = 2 * (2 * 128 * 80 + 64 * 80);   // 51200
  cudaFuncSetAttribute(mm_gemm<128, 1, false, false, false>, cudaFuncAttributeMaxDynamicSharedMemorySize, SM128);
  cudaFuncSetAttribute(mm_gemm<128, 0, false, false, false>, cudaFuncAttributeMaxDynamicSharedMemorySize, SM128);
  cudaFuncSetAttribute(mm_gemm<64, 1, false, false, false>,  cudaFuncAttributeMaxDynamicSharedMemorySize, SM64);
  cudaFuncSetAttribute(mm_gemm<128, 0, false, false, true>,  cudaFuncAttributeMaxDynamicSharedMemorySize, SM128);
  cudaFuncSetAttribute(mm_gemm<128, 1, true, true, false>,   cudaFuncAttributeMaxDynamicSharedMemorySize, SM128);
  cudaFuncSetAttribute(mm_gemm<128, 0, true, false, true>,   cudaFuncAttributeMaxDynamicSharedMemorySize, SM128);

  const ll SS = (ll)SQ * SQ;
  dim3 tb32(32, 8);

  embed_k<<<T_TOK, 128>>>(tokens, emb, X, Xh, Xl);

  for (int i = 0; i < NLAYER; i++) {
    const float* wq = WQ + (ll)i * HN * DM * 64;
    const float* wk = WK + (ll)i * HN * DM * 64;
    const float* wv = WV + (ll)i * HN * DM * 64;
    const float* wo = WO + (ll)i * DM * DM;
    const float* w1 = W1 + (ll)i * DM * DFF;
    const float* w2 = W2 + (ll)i * DFF * DM;

    tsplit_k<<<dim3(2, 16, 8), tb32>>>(wq, WQKVTh, 512, 64, 512 * 64, 64 * 512);
    tsplit_k<<<dim3(2, 16, 8), tb32>>>(wk, WQKVTh + 512 * 512, 512, 64, 512 * 64, 64 * 512);
    tsplit_k<<<dim3(2, 16, 8), tb32>>>(wv, WQKVTh + 1024 * 512, 512, 64, 512 * 64, 64 * 512);
    tsplit_k<<<dim3(16, 16, 1), tb32>>>(wo, WOTh, 512, 512, 0, 0);
    tsplit_k<<<dim3(64, 16, 1), tb32>>>(w1, W1Th, 512, 2048, 0, 0);
    tsplit_k<<<dim3(16, 64, 1), tb32>>>(w2, W2Th, 2048, 512, 0, 0);

    // QKV: [T,512] @ [1536,512]^T -> pairs [T,1536]
    mm_gemm<128, 1, false, false, false><<<dim3(128, 12, 1), 256, SM128>>>(
        Xh, Xl, WQKVTh, nullptr, QKVh, QKVl, nullptr, nullptr,
        512, 512, 512, 1536, 1.f, 1, 0, 0, 0, 0, 0, 0);

    vtrans_k<<<dim3(8, 32, 8), 256>>>(QKVh, VTh);

    // scores: per (h,b) Q@K^T/8 -> SC fp32 (A = Q pairs, B = K hi)
    mm_gemm<128, 0, false, false, false><<<dim3(4, 4, 256), 256, SM128>>>(
        QKVh, QKVl, QKVh + 512, SC, nullptr, nullptr, nullptr, nullptr,
        64, 1536, 1536, 512, 0.125f, 32,
        64, (ll)512 * 1536, 64, (ll)512 * 1536, 32 * SS, SS);

    softmax_k<<<HN * BATCH * SQ / 8, 256>>>(SC, Ph, Pl);

    // AV: per (h,b) P@VT^T -> ATT pairs [t][h*64+v]
    mm_gemm<64, 1, false, false, false><<<dim3(4, 1, 256), 256, SM64>>>(
        Ph, Pl, VTh, nullptr, ATTh, ATTl, nullptr, nullptr,
        512, 512, 512, 512, 1.f, 32,
        32 * SS, SS, (ll)32 * 64 * 512, 64 * 512, 64, (ll)512 * 512);

    // O-proj + residual -> Y fp32
    mm_gemm<128, 0, false, false, true><<<dim3(128, 4, 1), 256, SM128>>>(
        ATTh, ATTl, WOTh, Y, nullptr, nullptr, X, nullptr,
        512, 512, 512, 512, 1.f, 1, 0, 0, 0, 0, 0, 0);

    bn_part_k<<<256, DM>>>(Y, partS, partQ);
    bn_finish_k<<<1, DM>>>(partS, partQ, g1 + (ll)i * DM, be1 + (ll)i * DM, nrm);
    bn_apply_k<<<T_TOK * DM / 1024, 256>>>(Y, nrm, X, Xh, Xl);

    // FF1: relu(X@W1+b1) -> pairs
    mm_gemm<128, 1, true, true, false><<<dim3(128, 16, 1), 256, SM128>>>(
        Xh, Xl, W1Th, nullptr, Fh, Fl, nullptr, b1 + (ll)i * DFF,
        512, 512, 512, 2048, 1.f, 1, 0, 0, 0, 0, 0, 0);

    // FF2 + bias + residual -> Y fp32
    mm_gemm<128, 0, true, false, true><<<dim3(128, 4, 1), 256, SM128>>>(
        Fh, Fl, W2Th, Y, nullptr, nullptr, X, b2 + (ll)i * DM,
        2048, 2048, 2048, 512, 1.f, 1, 0, 0, 0, 0, 0, 0);

    bn_part_k<<<256, DM>>>(Y, partS, partQ);
    bn_finish_k<<<1, DM>>>(partS, partQ, g2 + (ll)i * DM, be2 + (ll)i * DM, nrm);
    bn_apply_k<<<T_TOK * DM / 1024, 256>>>(Y, nrm, X, Xh, Xl);
  }

  copy_k<<<T_TOK * DM / 1024, 256>>>(X, out);
}

// round 11
// speedup vs baseline: 5.8183x; 1.1913x over previous
#include <cuda_runtime.h>
#include <cuda_fp16.h>
#include <cstdint>

#define T_TOK 16384
#define DM    512
#define DFF   2048
#define HN    8
#define SQ    512
#define BATCH 32
#define NLAYER 6
#define EPSBN 1e-5f
typedef __half h16;
typedef long long ll;

// ---------------- asm helpers (plain sm_80+ PTX) ----------------
__device__ __forceinline__ uint32_t smem_u32(const void* p) {
  uint32_t a;
  asm("{ .reg .u64 t; cvta.to.shared.u64 t, %1; cvt.u32.u64 %0, t; }" : "=r"(a) : "l"(p));
  return a;
}
__device__ __forceinline__ void ldsm4(uint32_t* r, uint32_t a) {
  asm volatile("ldmatrix.sync.aligned.m8n8.x4.shared.b16 {%0,%1,%2,%3}, [%4];"
               : "=r"(r[0]), "=r"(r[1]), "=r"(r[2]), "=r"(r[3]) : "r"(a));
}
__device__ __forceinline__ void mma16816(float* c, const uint32_t* a, const uint32_t* b) {
  asm volatile(
      "mma.sync.aligned.m16n8k16.row.col.f32.f16.f16.f32 "
      "{%0,%1,%2,%3}, {%4,%5,%6,%7}, {%8,%9}, {%0,%1,%2,%3};"
      : "+f"(c[0]), "+f"(c[1]), "+f"(c[2]), "+f"(c[3])
      : "r"(a[0]), "r"(a[1]), "r"(a[2]), "r"(a[3]), "r"(b[0]), "r"(b[1]));
}
__device__ __forceinline__ void cpa16(uint32_t s, const void* g) {
  asm volatile("cp.async.cg.shared.global [%0], [%1], 16;" :: "r"(s), "l"(g));
}
__device__ __forceinline__ void split2(float v, h16& h, h16& l) {
  h = __float2half_rn(v);
  l = __float2half_rn(v - __half2float(h));
}
__device__ __forceinline__ uint32_t pack2(h16 a, h16 b) {
  return (uint32_t)__half_as_ushort(a) | ((uint32_t)__half_as_ushort(b) << 16);
}

// ---------------- Static scratch ----------------
__device__ float g_X[(size_t)T_TOK * DM];
__device__ float g_Y[(size_t)T_TOK * DM];
__device__ float g_SC[(size_t)BATCH * HN * SQ * SQ];
__device__ h16 g_Xh[(size_t)T_TOK * DM], g_Xl[(size_t)T_TOK * DM];
__device__ h16 g_QKVh[(size_t)T_TOK * 1536], g_QKVl[(size_t)T_TOK * 1536];
__device__ h16 g_VTh[(size_t)T_TOK * DM];
__device__ h16 g_Ph[(size_t)BATCH * HN * SQ * SQ];
__device__ h16 g_ATTh[(size_t)T_TOK * DM], g_ATTl[(size_t)T_TOK * DM];
__device__ h16 g_Fh[(size_t)T_TOK * DFF];
__device__ h16 g_WQKVTh[(size_t)NLAYER * 1536 * 512];
__device__ h16 g_WOTh[(size_t)NLAYER * 512 * 512];
__device__ h16 g_W1Th[(size_t)NLAYER * 2048 * 512];
__device__ h16 g_W2Th[(size_t)NLAYER * 512 * 2048];
__device__ float g_partS[256 * DM], g_partQ[256 * DM], g_nrm[2 * DM];

// ------- mma.sync fp16 GEMM: C = alpha*(Ah[+Al])@Bh^T (+bias)(+res)(relu) -------
// A:[M,K] fp16 (pair if PAIR) row-major; B:[N,K] fp16 row-major. M-tile 128, K mult 32.
// OUTM: 0 -> fp32 C ; 1 -> fp16 hi (Ch) + lo (Cl) for global cols < loCols.
template <int BN, bool PAIR, int OUTM, bool BIAS, bool RELU, bool RES>
__global__ void __launch_bounds__(256)
mm_gemm(const h16* __restrict__ Ah, const h16* __restrict__ Al,
        const h16* __restrict__ Bh,
        float* __restrict__ C, h16* __restrict__ Ch, h16* __restrict__ Cl,
        const float* __restrict__ Res, const float* __restrict__ bias, int loCols,
        int K, int lda, int ldb, int ldc, float alpha, int zInner,
        ll sAo, ll sAi, ll sBo, ll sBi, ll sCo, ll sCi) {
  constexpr int WRM = (BN == 128) ? 2 : 4;
  constexpr int WRN = 8 / WRM;
  constexpr int WTM = 128 / WRM;
  constexpr int WTN = BN / WRN;
  constexpr int MT = WTM / 16;
  constexpr int NT = WTN / 8;
  constexpr int AB = 128 * 80;                       // one A tile (80B padded rows)
  constexpr int BB = BN * 80;
  constexpr int NA = PAIR ? 2 : 1;
  constexpr int SB = NA * AB + BB;                   // stage bytes

  extern __shared__ char dynsm[];
  const uint32_t sb = smem_u32(dynsm);

  const int tid = threadIdx.x, wid = tid >> 5, lane = tid & 31;
  const int wm = wid / WRN, wn = wid % WRN;
  const int zo = blockIdx.z / zInner, zi = blockIdx.z % zInner;

  const h16* A_h = Ah + zo * sAo + zi * sAi + (ll)blockIdx.x * 128 * lda;
  const h16* A_l = PAIR ? (Al + zo * sAo + zi * sAi + (ll)blockIdx.x * 128 * lda) : nullptr;
  const h16* B_h = Bh + zo * sBo + zi * sBi + (ll)blockIdx.y * BN * ldb;
  const ll coff = zo * sCo + zi * sCi + (ll)blockIdx.x * 128 * ldc + (ll)blockIdx.y * BN;

  float acc[MT][NT][4];
#pragma unroll
  for (int i = 0; i < MT; i++)
#pragma unroll
    for (int j = 0; j < NT; j++)
#pragma unroll
      for (int e = 0; e < 4; e++) acc[i][j][e] = 0.f;

  auto load_stage = [&](int kt, int s) {
    const int k0 = kt * 32;
    const uint32_t s0 = sb + s * SB;
#pragma unroll 2
    for (int i = tid; i < 128 * 4; i += 256) {
      const int r = i >> 2, c = i & 3;
      const uint32_t so = (uint32_t)(r * 80 + c * 16);
      const ll go = (ll)r * lda + k0 + c * 8;
      cpa16(s0 + so, A_h + go);
      if (PAIR) cpa16(s0 + AB + so, A_l + go);
    }
#pragma unroll
    for (int i = tid; i < BN * 4; i += 256) {
      const int r = i >> 2, c = i & 3;
      cpa16(s0 + NA * AB + (uint32_t)(r * 80 + c * 16), B_h + (ll)r * ldb + k0 + c * 8);
    }
  };

  const int KT = K >> 5;
  load_stage(0, 0);
  asm volatile("cp.async.commit_group;");

  const uint32_t arow = (uint32_t)(lane & 15);
  const uint32_t acol = (uint32_t)((lane >> 4) * 16);
  const uint32_t brow = (uint32_t)((lane & 7) + ((lane >> 4) << 3));
  const uint32_t bcol = (uint32_t)(((lane >> 3) & 1) * 16);

  for (int kt = 0; kt < KT; kt++) {
    if (kt + 1 < KT) {
      load_stage(kt + 1, (kt + 1) & 1);
      asm volatile("cp.async.commit_group;");
      asm volatile("cp.async.wait_group 1;");
    } else {
      asm volatile("cp.async.wait_group 0;");
    }
    __syncthreads();

    const uint32_t abase = sb + (kt & 1) * SB;
    const uint32_t bbase = abase + NA * AB;
#pragma unroll
    for (int ks = 0; ks < 2; ks++) {
      uint32_t aH[MT][4], aL[MT][4], bH[NT][2];
#pragma unroll
      for (int mt = 0; mt < MT; mt++) {
        const uint32_t ad = abase + (wm * WTM + mt * 16 + arow) * 80 + ks * 32 + acol;
        ldsm4(aH[mt], ad);
        if (PAIR) ldsm4(aL[mt], ad + AB);
      }
#pragma unroll
      for (int p = 0; p < NT / 2; p++) {
        const uint32_t bd = bbase + (wn * WTN + p * 16 + brow) * 80 + ks * 32 + bcol;
        uint32_t t[4];
        ldsm4(t, bd);
        bH[2 * p][0] = t[0]; bH[2 * p][1] = t[1];
        bH[2 * p + 1][0] = t[2]; bH[2 * p + 1][1] = t[3];
      }
#pragma unroll
      for (int mt = 0; mt < MT; mt++)
#pragma unroll
        for (int nt = 0; nt < NT; nt++) {
          mma16816(acc[mt][nt], aH[mt], bH[nt]);
          if (PAIR) mma16816(acc[mt][nt], aL[mt], bH[nt]);
        }
    }
    __syncthreads();
  }

  // ---------------- epilogue ----------------
#pragma unroll
  for (int mt = 0; mt < MT; mt++) {
#pragma unroll
    for (int nt = 0; nt < NT; nt++) {
      const int r0 = wm * WTM + mt * 16 + (lane >> 2);
      const int cc = wn * WTN + nt * 8 + (lane & 3) * 2;
      float v0 = acc[mt][nt][0] * alpha, v1 = acc[mt][nt][1] * alpha;
      float v2 = acc[mt][nt][2] * alpha, v3 = acc[mt][nt][3] * alpha;
      if (BIAS) {
        const float b0v = bias[(ll)blockIdx.y * BN + cc];
        const float b1v = bias[(ll)blockIdx.y * BN + cc + 1];
        v0 += b0v; v2 += b0v; v1 += b1v; v3 += b1v;
      }
#pragma unroll
      for (int half = 0; half < 2; half++) {
        const int r = r0 + half * 8;
        float x0 = half ? v2 : v0, x1 = half ? v3 : v1;
        const ll go = coff + (ll)r * ldc + cc;
        if (RES) {
          const float2 rr = *reinterpret_cast<const float2*>(Res + go);
          x0 += rr.x; x1 += rr.y;
        }
        if (RELU) { x0 = fmaxf(x0, 0.f); x1 = fmaxf(x1, 0.f); }
        if (OUTM == 0) {
          *reinterpret_cast<float2*>(C + go) = make_float2(x0, x1);
        } else {
          h16 h0, h1, l0, l1;
          split2(x0, h0, l0); split2(x1, h1, l1);
          *reinterpret_cast<uint32_t*>(Ch + go) = pack2(h0, h1);
          if (blockIdx.y * BN + cc < (unsigned)loCols)
            *reinterpret_cast<uint32_t*>(Cl + go) = pack2(l0, l1);
        }
      }
    }
  }
}

// -------- transpose + round: fp32 [R,C] -> fp16 hi [C,R]; batched 2-level z ------
__global__ void tsplit_k(const float* __restrict__ in, h16* __restrict__ oh,
                         int R, int C, int zInner,
                         ll sIno, ll sIni, ll sOuto, ll sOuti) {
  __shared__ float t[32][33];
  const int zo = blockIdx.z / zInner, zi = blockIdx.z % zInner;
  const float* I = in + zo * sIno + zi * sIni;
  h16* O = oh + zo * sOuto + zi * sOuti;
  int c0 = blockIdx.x * 32, r0 = blockIdx.y * 32;
#pragma unroll
  for (int i = 0; i < 4; i++)
    t[threadIdx.y + i * 8][threadIdx.x] =
        I[(ll)(r0 + threadIdx.y + i * 8) * C + c0 + threadIdx.x];
  __syncthreads();
#pragma unroll
  for (int i = 0; i < 4; i++) {
    int c = c0 + threadIdx.y + i * 8;
    O[(ll)c * R + r0 + threadIdx.x] = __float2half_rn(t[threadIdx.x][threadIdx.y + i * 8]);
  }
}

// -------- V transpose: QKV hi [T,1536] -> VT hi [(h,b)][64][512] --------
__global__ void vtrans_k(const h16* __restrict__ ih, h16* __restrict__ oh) {
  __shared__ h16 th[64][72];
  int h = blockIdx.x, b = blockIdx.y, s0 = blockIdx.z * 64;
  int tid = threadIdx.x;
  for (int i = tid; i < 64 * 8; i += 256) {
    int row = i >> 3, c8 = i & 7;
    ll gi = (ll)(b * 512 + s0 + row) * 1536 + 1024 + h * 64 + c8 * 8;
    *reinterpret_cast<uint4*>(&th[row][c8 * 8]) = *reinterpret_cast<const uint4*>(ih + gi);
  }
  __syncthreads();
  for (int i = tid; i < 64 * 64; i += 256) {
    int v = i >> 6, s = i & 63;
    oh[((ll)(h * 32 + b) * 64 + v) * 512 + s0 + s] = th[s][v];
  }
}

// ---------------- elementwise ----------------
__global__ void embed_k(const int* __restrict__ tok, const float* __restrict__ emb,
                        float* __restrict__ X, h16* __restrict__ Xh, h16* __restrict__ Xl) {
  int t = blockIdx.x, c4 = threadIdx.x;
  float4 v = reinterpret_cast<const float4*>(emb + (ll)tok[t] * DM)[c4];
  v.x *= 8.f; v.y *= 8.f; v.z *= 8.f; v.w *= 8.f;
  ll go = (ll)t * DM + c4 * 4;
  *reinterpret_cast<float4*>(X + go) = v;
  h16 h0, h1, h2, h3, l0, l1, l2, l3;
  split2(v.x, h0, l0); split2(v.y, h1, l1); split2(v.z, h2, l2); split2(v.w, h3, l3);
  *reinterpret_cast<uint2*>(Xh + go) = make_uint2(pack2(h0, h1), pack2(h2, h3));
  *reinterpret_cast<uint2*>(Xl + go) = make_uint2(pack2(l0, l1), pack2(l2, l3));
}

__global__ void softmax_k(const float* __restrict__ S, h16* __restrict__ Ph) {
  int warp = threadIdx.x >> 5, lane = threadIdx.x & 31;
  ll row = (ll)blockIdx.x * 8 + warp;
  const float* p = S + row * 512;
  float4 v[4];
  float mx = -1e30f;
#pragma unroll
  for (int it = 0; it < 4; it++) {
    v[it] = *reinterpret_cast<const float4*>(p + it * 128 + lane * 4);
    mx = fmaxf(mx, fmaxf(fmaxf(v[it].x, v[it].y), fmaxf(v[it].z, v[it].w)));
  }
#pragma unroll
  for (int o = 16; o; o >>= 1) mx = fmaxf(mx, __shfl_xor_sync(0xffffffffu, mx, o));
  float sum = 0.f;
#pragma unroll
  for (int it = 0; it < 4; it++) {
    v[it].x = __expf(v[it].x - mx); v[it].y = __expf(v[it].y - mx);
    v[it].z = __expf(v[it].z - mx); v[it].w = __expf(v[it].w - mx);
    sum += v[it].x + v[it].y + v[it].z + v[it].w;
  }
#pragma unroll
  for (int o = 16; o; o >>= 1) sum += __shfl_xor_sync(0xffffffffu, sum, o);
  float inv = 1.f / sum;
#pragma unroll
  for (int it = 0; it < 4; it++) {
    h16 h0 = __float2half_rn(v[it].x * inv), h1 = __float2half_rn(v[it].y * inv);
    h16 h2 = __float2half_rn(v[it].z * inv), h3 = __float2half_rn(v[it].w * inv);
    *reinterpret_cast<uint2*>(Ph + row * 512 + it * 128 + lane * 4) =
        make_uint2(pack2(h0, h1), pack2(h2, h3));
  }
}

__global__ void bn_part_k(const float* __restrict__ Y, float* __restrict__ pS,
                          float* __restrict__ pQ) {
  int c = threadIdx.x, p = blockIdx.x;
  const float* base = Y + (ll)p * 64 * DM + c;
  float s = 0.f, q = 0.f;
#pragma unroll 8
  for (int r = 0; r < 64; r++) { float v = base[(ll)r * DM]; s += v; q += v * v; }
  pS[p * DM + c] = s; pQ[p * DM + c] = q;
}
__global__ void bn_finish_k(const float* __restrict__ pS, const float* __restrict__ pQ,
                            const float* __restrict__ g, const float* __restrict__ be,
                            float* __restrict__ nrm) {
  int c = threadIdx.x;
  float s = 0.f, q = 0.f;
  for (int p = 0; p < 256; p++) { s += pS[p * DM + c]; q += pQ[p * DM + c]; }
  const float invN = 1.f / (float)T_TOK;
  float mean = s * invN, var = q * invN - mean * mean;
  float a = g[c] * rsqrtf(var + EPSBN);
  nrm[c] = a; nrm[DM + c] = be[c] - mean * a;
}
__global__ void bn_apply_k(const float* __restrict__ Y, const float* __restrict__ nrm,
                           float* __restrict__ X, h16* __restrict__ Xh, h16* __restrict__ Xl) {
  ll idx = ((ll)blockIdx.x * blockDim.x + threadIdx.x) * 4;
  int c = (int)(idx & (DM - 1));
  float4 v = *reinterpret_cast<const float4*>(Y + idx);
  float4 o;
  o.x = v.x * nrm[c] + nrm[DM + c];
  o.y = v.y * nrm[c + 1] + nrm[DM + c + 1];
  o.z = v.z * nrm[c + 2] + nrm[DM + c + 2];
  o.w = v.w * nrm[c + 3] + nrm[DM + c + 3];
  *reinterpret_cast<float4*>(X + idx) = o;
  h16 h0, h1, h2, h3, l0, l1, l2, l3;
  split2(o.x, h0, l0); split2(o.y, h1, l1); split2(o.z, h2, l2); split2(o.w, h3, l3);
  *reinterpret_cast<uint2*>(Xh + idx) = make_uint2(pack2(h0, h1), pack2(h2, h3));
  *reinterpret_cast<uint2*>(Xl + idx) = make_uint2(pack2(l0, l1), pack2(l2, l3));
}
__global__ void copy_k(const float* __restrict__ X, float* __restrict__ out) {
  ll idx = ((ll)blockIdx.x * blockDim.x + threadIdx.x) * 4;
  *reinterpret_cast<float4*>(out + idx) = *reinterpret_cast<const float4*>(X + idx);
}

// ---------------- host ----------------
#define GETP(var, sym) void* p_##var; cudaGetSymbolAddress(&p_##var, sym)
extern "C" void kernel_launch(void* const* d_in, const int* in_sizes, int n_in,
                              void* d_out, int out_size) {
  (void)in_sizes; (void)n_in; (void)out_size;
  const int* tokens = (const int*)d_in[0];
  const float* emb = (const float*)d_in[1];
  const float *WQ = (const float*)d_in[2], *WK = (const float*)d_in[3];
  const float *WV = (const float*)d_in[4], *WO = (const float*)d_in[5];
  const float *g1 = (const float*)d_in[6], *be1 = (const float*)d_in[7];
  const float *W1 = (const float*)d_in[8], *b1 = (const float*)d_in[9];
  const float *W2 = (const float*)d_in[10], *b2 = (const float*)d_in[11];
  const float *g2 = (const float*)d_in[12], *be2 = (const float*)d_in[13];
  float* out = (float*)d_out;

  GETP(X, g_X); GETP(Y, g_Y); GETP(SC, g_SC);
  GETP(Xh, g_Xh); GETP(Xl, g_Xl); GETP(QKVh, g_QKVh); GETP(QKVl, g_QKVl);
  GETP(VTh, g_VTh); GETP(Ph, g_Ph);
  GETP(ATTh, g_ATTh); GETP(ATTl, g_ATTl); GETP(Fh, g_Fh);
  GETP(WQKVTh, g_WQKVTh); GETP(WOTh, g_WOTh);
  GETP(W1Th, g_W1Th); GETP(W2Th, g_W2Th);
  GETP(pS, g_partS); GETP(pQ, g_partQ); GETP(nrm, g_nrm);
  float *X = (float*)p_X, *Y = (float*)p_Y, *SC = (float*)p_SC;
  h16 *Xh = (h16*)p_Xh, *Xl = (h16*)p_Xl, *QKVh = (h16*)p_QKVh, *QKVl = (h16*)p_QKVl;
  h16 *VTh = (h16*)p_VTh, *Ph = (h16*)p_Ph;
  h16 *ATTh = (h16*)p_ATTh, *ATTl = (h16*)p_ATTl, *Fh = (h16*)p_Fh;
  h16 *WQKVTa = (h16*)p_WQKVTh, *WOTa = (h16*)p_WOTh;
  h16 *W1Ta = (h16*)p_W1Th, *W2Ta = (h16*)p_W2Th;
  float *partS = (float*)p_pS, *partQ = (float*)p_pQ, *nrm = (float*)p_nrm;

  const int SM_P128 = 2 * (2 * 128 * 80 + 128 * 80);  // pair, BN=128: 61440
  const int SM_S128 = 2 * (128 * 80 + 128 * 80);      // single, BN=128: 40960
  const int SM_S64  = 2 * (128 * 80 + 64 * 80);       // single, BN=64: 30720
  cudaFuncSetAttribute(mm_gemm<128, true, 1, false, false, false>, cudaFuncAttributeMaxDynamicSharedMemorySize, SM_P128);
  cudaFuncSetAttribute(mm_gemm<128, true, 0, false, false, false>, cudaFuncAttributeMaxDynamicSharedMemorySize, SM_P128);
  cudaFuncSetAttribute(mm_gemm<64, false, 1, false, false, false>, cudaFuncAttributeMaxDynamicSharedMemorySize, SM_S64);
  cudaFuncSetAttribute(mm_gemm<128, true, 0, false, false, true>,  cudaFuncAttributeMaxDynamicSharedMemorySize, SM_P128);
  cudaFuncSetAttribute(mm_gemm<128, true, 1, true, true, false>,   cudaFuncAttributeMaxDynamicSharedMemorySize, SM_P128);
  cudaFuncSetAttribute(mm_gemm<128, false, 0, true, false, true>,  cudaFuncAttributeMaxDynamicSharedMemorySize, SM_S128);

  const ll SS = (ll)SQ * SQ;
  dim3 tb32(32, 8);

  embed_k<<<T_TOK, 128>>>(tokens, emb, X, Xh, Xl);

  // ---- batched weight prep for ALL layers ----
  // WQ/WK/WV: in [L][H][512][64]; out [L][qkv][h][64][512] inside [L][1536][512]
  tsplit_k<<<dim3(2, 16, NLAYER * HN), tb32>>>(WQ, WQKVTa, 512, 64, HN,
      (ll)HN * 512 * 64, (ll)512 * 64, (ll)1536 * 512, (ll)64 * 512);
  tsplit_k<<<dim3(2, 16, NLAYER * HN), tb32>>>(WK, WQKVTa + 512 * 512, 512, 64, HN,
      (ll)HN * 512 * 64, (ll)512 * 64, (ll)1536 * 512, (ll)64 * 512);
  tsplit_k<<<dim3(2, 16, NLAYER * HN), tb32>>>(WV, WQKVTa + 1024 * 512, 512, 64, HN,
      (ll)HN * 512 * 64, (ll)512 * 64, (ll)1536 * 512, (ll)64 * 512);
  // FIX R9 bug: per-layer stride must be in the OUTER slot when zInner == 1
  tsplit_k<<<dim3(16, 16, NLAYER), tb32>>>(WO, WOTa, 512, 512, 1,
      (ll)512 * 512, 0, (ll)512 * 512, 0);
  tsplit_k<<<dim3(64, 16, NLAYER), tb32>>>(W1, W1Ta, 512, 2048, 1,
      (ll)512 * 2048, 0, (ll)2048 * 512, 0);
  tsplit_k<<<dim3(16, 64, NLAYER), tb32>>>(W2, W2Ta, 2048, 512, 1,
      (ll)2048 * 512, 0, (ll)512 * 2048, 0);

  for (int i = 0; i < NLAYER; i++) {
    const h16* WQKVT = WQKVTa + (ll)i * 1536 * 512;
    const h16* WOT = WOTa + (ll)i * 512 * 512;
    const h16* W1T = W1Ta + (ll)i * 2048 * 512;
    const h16* W2T = W2Ta + (ll)i * 512 * 2048;

    // QKV: [T,512] @ [1536,512]^T ; lo written only for Q cols (<512)
    mm_gemm<128, true, 1, false, false, false><<<dim3(128, 12, 1), 256, SM_P128>>>(
        Xh, Xl, WQKVT, nullptr, QKVh, QKVl, nullptr, nullptr, 512,
        512, 512, 512, 1536, 1.f, 1, 0, 0, 0, 0, 0, 0);

    vtrans_k<<<dim3(8, 32, 8), 256>>>(QKVh, VTh);

    // scores: per (h,b) Q@K^T/8 -> SC fp32 (A = Q pair, B = K hi)
    mm_gemm<128, true, 0, false, false, false><<<dim3(4, 4, 256), 256, SM_P128>>>(
        QKVh, QKVl, QKVh + 512, SC, nullptr, nullptr, nullptr, nullptr, 0,
        64, 1536, 1536, 512, 0.125f, 32,
        64, (ll)512 * 1536, 64, (ll)512 * 1536, 32 * SS, SS);

    softmax_k<<<HN * BATCH * SQ / 8, 256>>>(SC, Ph);

    // AV: per (h,b) P(hi)@VT^T -> ATT pairs [t][h*64+v]
    mm_gemm<64, false, 1, false, false, false><<<dim3(4, 1, 256), 256, SM_S64>>>(
        Ph, nullptr, VTh, nullptr, ATTh, ATTl, nullptr, nullptr, 1 << 30,
        512, 512, 512, 512, 1.f, 32,
        32 * SS, SS, (ll)32 * 64 * 512, 64 * 512, 64, (ll)512 * 512);

    // O-proj + residual -> Y fp32
    mm_gemm<128, true, 0, false, false, true><<<dim3(128, 4, 1), 256, SM_P128>>>(
        ATTh, ATTl, WOT, Y, nullptr, nullptr, X, nullptr, 0,
        512, 512, 512, 512, 1.f, 1, 0, 0, 0, 0, 0, 0);

    bn_part_k<<<256, DM>>>(Y, partS, partQ);
    bn_finish_k<<<1, DM>>>(partS, partQ, g1 + (ll)i * DM, be1 + (ll)i * DM, nrm);
    bn_apply_k<<<T_TOK * DM / 1024, 256>>>(Y, nrm, X, Xh, Xl);

    // FF1: relu(X@W1+b1) -> Fh (hi only)
    mm_gemm<128, true, 1, true, true, false><<<dim3(128, 16, 1), 256, SM_P128>>>(
        Xh, Xl, W1T, nullptr, Fh, nullptr, nullptr, b1 + (ll)i * DFF, 0,
        512, 512, 512, 2048, 1.f, 1, 0, 0, 0, 0, 0, 0);

    // FF2 + bias + residual -> Y fp32 (A = Fh single)
    mm_gemm<128, false, 0, true, false, true><<<dim3(128, 4, 1), 256, SM_S128>>>(
        Fh, nullptr, W2T, Y, nullptr, nullptr, X, b2 + (ll)i * DM, 0,
        2048, 2048, 2048, 512, 1.f, 1, 0, 0, 0, 0, 0, 0);

    bn_part_k<<<256, DM>>>(Y, partS, partQ);
    bn_finish_k<<<1, DM>>>(partS, partQ, g2 + (ll)i * DM, be2 + (ll)i * DM, nrm);
    bn_apply_k<<<T_TOK * DM / 1024, 256>>>(Y, nrm, X, Xh, Xl);
  }

  copy_k<<<T_TOK * DM / 1024, 256>>>(X, out);
}

// round 13
// speedup vs baseline: 7.4703x; 1.2839x over previous
#include <cuda_runtime.h>
#include <cuda_fp16.h>
#include <cstdint>

#define T_TOK 16384
#define DM    512
#define DFF   2048
#define HN    8
#define SQ    512
#define BATCH 32
#define NLAYER 6
#define EPSBN 1e-5f
typedef __half h16;
typedef long long ll;

// ---------------- asm helpers (plain sm_80+ PTX) ----------------
__device__ __forceinline__ uint32_t smem_u32(const void* p) {
  uint32_t a;
  asm("{ .reg .u64 t; cvta.to.shared.u64 t, %1; cvt.u32.u64 %0, t; }" : "=r"(a) : "l"(p));
  return a;
}
__device__ __forceinline__ void ldsm4(uint32_t* r, uint32_t a) {
  asm volatile("ldmatrix.sync.aligned.m8n8.x4.shared.b16 {%0,%1,%2,%3}, [%4];"
               : "=r"(r[0]), "=r"(r[1]), "=r"(r[2]), "=r"(r[3]) : "r"(a));
}
__device__ __forceinline__ void mma16816(float* c, const uint32_t* a, const uint32_t* b) {
  asm volatile(
      "mma.sync.aligned.m16n8k16.row.col.f32.f16.f16.f32 "
      "{%0,%1,%2,%3}, {%4,%5,%6,%7}, {%8,%9}, {%0,%1,%2,%3};"
      : "+f"(c[0]), "+f"(c[1]), "+f"(c[2]), "+f"(c[3])
      : "r"(a[0]), "r"(a[1]), "r"(a[2]), "r"(a[3]), "r"(b[0]), "r"(b[1]));
}
__device__ __forceinline__ void cpa16(uint32_t s, const void* g) {
  asm volatile("cp.async.cg.shared.global [%0], [%1], 16;" :: "r"(s), "l"(g));
}
__device__ __forceinline__ uint32_t pack2(h16 a, h16 b) {
  return (uint32_t)__half_as_ushort(a) | ((uint32_t)__half_as_ushort(b) << 16);
}

// ---------------- Static scratch ----------------
__device__ float g_X[(size_t)T_TOK * DM];
__device__ float g_Y[(size_t)T_TOK * DM];
__device__ float g_SC[(size_t)BATCH * HN * SQ * SQ];
__device__ h16 g_Xh[(size_t)T_TOK * DM];
__device__ h16 g_QKVh[(size_t)T_TOK * 1536];
__device__ h16 g_VTh[(size_t)T_TOK * DM];
__device__ h16 g_Ph[(size_t)BATCH * HN * SQ * SQ];
__device__ h16 g_ATTh[(size_t)T_TOK * DM];
__device__ h16 g_Fh[(size_t)T_TOK * DFF];
__device__ h16 g_WQKVTh[(size_t)NLAYER * 1536 * 512];
__device__ h16 g_WOTh[(size_t)NLAYER * 512 * 512];
__device__ h16 g_W1Th[(size_t)NLAYER * 2048 * 512];
__device__ h16 g_W2Th[(size_t)NLAYER * 512 * 2048];
__device__ float g_partS[256 * DM], g_partQ[256 * DM], g_nrm[2 * DM];

// ------- mma.sync fp16 GEMM: C = alpha*Ah@Bh^T (+bias)(+res)(relu) -------
// A:[M,K] fp16 row-major; B:[N,K] fp16 row-major. M-tile 128, K mult of 32.
// OUTM: 0 -> fp32 C ; 1 -> fp16 Ch.
template <int BN, int OUTM, bool BIAS, bool RELU, bool RES>
__global__ void __launch_bounds__(256)
mm_gemm(const h16* __restrict__ Ah, const h16* __restrict__ Bh,
        float* __restrict__ C, h16* __restrict__ Ch,
        const float* __restrict__ Res, const float* __restrict__ bias,
        int K, int lda, int ldb, int ldc, float alpha, int zInner,
        ll sAo, ll sAi, ll sBo, ll sBi, ll sCo, ll sCi) {
  constexpr int WRM = (BN == 128) ? 2 : 4;
  constexpr int WRN = 8 / WRM;
  constexpr int WTM = 128 / WRM;
  constexpr int WTN = BN / WRN;
  constexpr int MT = WTM / 16;
  constexpr int NT = WTN / 8;
  constexpr int AB = 128 * 80;          // A tile bytes (80B padded rows)
  constexpr int BB = BN * 80;
  constexpr int SB = AB + BB;           // stage bytes

  extern __shared__ char dynsm[];
  const uint32_t sb = smem_u32(dynsm);

  const int tid = threadIdx.x, wid = tid >> 5, lane = tid & 31;
  const int wm = wid / WRN, wn = wid % WRN;
  const int zo = blockIdx.z / zInner, zi = blockIdx.z % zInner;

  const h16* A_h = Ah + zo * sAo + zi * sAi + (ll)blockIdx.x * 128 * lda;
  const h16* B_h = Bh + zo * sBo + zi * sBi + (ll)blockIdx.y * BN * ldb;
  const ll coff = zo * sCo + zi * sCi + (ll)blockIdx.x * 128 * ldc + (ll)blockIdx.y * BN;

  float acc[MT][NT][4];
#pragma unroll
  for (int i = 0; i < MT; i++)
#pragma unroll
    for (int j = 0; j < NT; j++)
#pragma unroll
      for (int e = 0; e < 4; e++) acc[i][j][e] = 0.f;

  auto load_stage = [&](int kt, int s) {
    const int k0 = kt * 32;
    const uint32_t s0 = sb + s * SB;
#pragma unroll 2
    for (int i = tid; i < 128 * 4; i += 256) {
      const int r = i >> 2, c = i & 3;
      cpa16(s0 + (uint32_t)(r * 80 + c * 16), A_h + (ll)r * lda + k0 + c * 8);
    }
#pragma unroll
    for (int i = tid; i < BN * 4; i += 256) {
      const int r = i >> 2, c = i & 3;
      cpa16(s0 + AB + (uint32_t)(r * 80 + c * 16), B_h + (ll)r * ldb + k0 + c * 8);
    }
  };

  const int KT = K >> 5;
  load_stage(0, 0);
  asm volatile("cp.async.commit_group;");

  const uint32_t arow = (uint32_t)(lane & 15);
  const uint32_t acol = (uint32_t)((lane >> 4) * 16);
  const uint32_t brow = (uint32_t)((lane & 7) + ((lane >> 4) << 3));
  const uint32_t bcol = (uint32_t)(((lane >> 3) & 1) * 16);

  for (int kt = 0; kt < KT; kt++) {
    if (kt + 1 < KT) {
      load_stage(kt + 1, (kt + 1) & 1);
      asm volatile("cp.async.commit_group;");
      asm volatile("cp.async.wait_group 1;");
    } else {
      asm volatile("cp.async.wait_group 0;");
    }
    __syncthreads();

    const uint32_t abase = sb + (kt & 1) * SB;
    const uint32_t bbase = abase + AB;
#pragma unroll
    for (int ks = 0; ks < 2; ks++) {
      uint32_t aH[MT][4], bH[NT][2];
#pragma unroll
      for (int mt = 0; mt < MT; mt++) {
        ldsm4(aH[mt], abase + (wm * WTM + mt * 16 + arow) * 80 + ks * 32 + acol);
      }
#pragma unroll
      for (int p = 0; p < NT / 2; p++) {
        uint32_t t[4];
        ldsm4(t, bbase + (wn * WTN + p * 16 + brow) * 80 + ks * 32 + bcol);
        bH[2 * p][0] = t[0]; bH[2 * p][1] = t[1];
        bH[2 * p + 1][0] = t[2]; bH[2 * p + 1][1] = t[3];
      }
#pragma unroll
      for (int mt = 0; mt < MT; mt++)
#pragma unroll
        for (int nt = 0; nt < NT; nt++)
          mma16816(acc[mt][nt], aH[mt], bH[nt]);
    }
    __syncthreads();
  }

  // ---------------- epilogue ----------------
#pragma unroll
  for (int mt = 0; mt < MT; mt++) {
#pragma unroll
    for (int nt = 0; nt < NT; nt++) {
      const int r0 = wm * WTM + mt * 16 + (lane >> 2);
      const int cc = wn * WTN + nt * 8 + (lane & 3) * 2;
      float v0 = acc[mt][nt][0] * alpha, v1 = acc[mt][nt][1] * alpha;
      float v2 = acc[mt][nt][2] * alpha, v3 = acc[mt][nt][3] * alpha;
      if (BIAS) {
        const float b0v = bias[(ll)blockIdx.y * BN + cc];
        const float b1v = bias[(ll)blockIdx.y * BN + cc + 1];
        v0 += b0v; v2 += b0v; v1 += b1v; v3 += b1v;
      }
#pragma unroll
      for (int half = 0; half < 2; half++) {
        const int r = r0 + half * 8;
        float x0 = half ? v2 : v0, x1 = half ? v3 : v1;
        const ll go = coff + (ll)r * ldc + cc;
        if (RES) {
          const float2 rr = *reinterpret_cast<const float2*>(Res + go);
          x0 += rr.x; x1 += rr.y;
        }
        if (RELU) { x0 = fmaxf(x0, 0.f); x1 = fmaxf(x1, 0.f); }
        if (OUTM == 0) {
          *reinterpret_cast<float2*>(C + go) = make_float2(x0, x1);
        } else {
          *reinterpret_cast<uint32_t*>(Ch + go) =
              pack2(__float2half_rn(x0), __float2half_rn(x1));
        }
      }
    }
  }
}

// -------- transpose + round: fp32 [R,C] -> fp16 hi [C,R]; batched 2-level z ------
__global__ void tsplit_k(const float* __restrict__ in, h16* __restrict__ oh,
                         int R, int C, int zInner,
                         ll sIno, ll sIni, ll sOuto, ll sOuti) {
  __shared__ float t[32][33];
  const int zo = blockIdx.z / zInner, zi = blockIdx.z % zInner;
  const float* I = in + zo * sIno + zi * sIni;
  h16* O = oh + zo * sOuto + zi * sOuti;
  int c0 = blockIdx.x * 32, r0 = blockIdx.y * 32;
#pragma unroll
  for (int i = 0; i < 4; i++)
    t[threadIdx.y + i * 8][threadIdx.x] =
        I[(ll)(r0 + threadIdx.y + i * 8) * C + c0 + threadIdx.x];
  __syncthreads();
#pragma unroll
  for (int i = 0; i < 4; i++) {
    int c = c0 + threadIdx.y + i * 8;
    O[(ll)c * R + r0 + threadIdx.x] = __float2half_rn(t[threadIdx.x][threadIdx.y + i * 8]);
  }
}

// -------- V transpose: QKV hi [T,1536] -> VT hi [(h,b)][64][512] --------
__global__ void vtrans_k(const h16* __restrict__ ih, h16* __restrict__ oh) {
  __shared__ h16 th[64][72];
  int h = blockIdx.x, b = blockIdx.y, s0 = blockIdx.z * 64;
  int tid = threadIdx.x;
  for (int i = tid; i < 64 * 8; i += 256) {
    int row = i >> 3, c8 = i & 7;
    ll gi = (ll)(b * 512 + s0 + row) * 1536 + 1024 + h * 64 + c8 * 8;
    *reinterpret_cast<uint4*>(&th[row][c8 * 8]) = *reinterpret_cast<const uint4*>(ih + gi);
  }
  __syncthreads();
  for (int i = tid; i < 64 * 64; i += 256) {
    int v = i >> 6, s = i & 63;
    oh[((ll)(h * 32 + b) * 64 + v) * 512 + s0 + s] = th[s][v];
  }
}

// ---------------- elementwise ----------------
__global__ void embed_k(const int* __restrict__ tok, const float* __restrict__ emb,
                        float* __restrict__ X, h16* __restrict__ Xh) {
  int t = blockIdx.x, c4 = threadIdx.x;
  float4 v = reinterpret_cast<const float4*>(emb + (ll)tok[t] * DM)[c4];
  v.x *= 8.f; v.y *= 8.f; v.z *= 8.f; v.w *= 8.f;
  ll go = (ll)t * DM + c4 * 4;
  *reinterpret_cast<float4*>(X + go) = v;
  *reinterpret_cast<uint2*>(Xh + go) = make_uint2(
      pack2(__float2half_rn(v.x), __float2half_rn(v.y)),
      pack2(__float2half_rn(v.z), __float2half_rn(v.w)));
}

__global__ void softmax_k(const float* __restrict__ S, h16* __restrict__ Ph) {
  int warp = threadIdx.x >> 5, lane = threadIdx.x & 31;
  ll row = (ll)blockIdx.x * 8 + warp;
  const float* p = S + row * 512;
  float4 v[4];
  float mx = -1e30f;
#pragma unroll
  for (int it = 0; it < 4; it++) {
    v[it] = *reinterpret_cast<const float4*>(p + it * 128 + lane * 4);
    mx = fmaxf(mx, fmaxf(fmaxf(v[it].x, v[it].y), fmaxf(v[it].z, v[it].w)));
  }
#pragma unroll
  for (int o = 16; o; o >>= 1) mx = fmaxf(mx, __shfl_xor_sync(0xffffffffu, mx, o));
  float sum = 0.f;
#pragma unroll
  for (int it = 0; it < 4; it++) {
    v[it].x = __expf(v[it].x - mx); v[it].y = __expf(v[it].y - mx);
    v[it].z = __expf(v[it].z - mx); v[it].w = __expf(v[it].w - mx);
    sum += v[it].x + v[it].y + v[it].z + v[it].w;
  }
#pragma unroll
  for (int o = 16; o; o >>= 1) sum += __shfl_xor_sync(0xffffffffu, sum, o);
  float inv = 1.f / sum;
#pragma unroll
  for (int it = 0; it < 4; it++) {
    *reinterpret_cast<uint2*>(Ph + row * 512 + it * 128 + lane * 4) = make_uint2(
        pack2(__float2half_rn(v[it].x * inv), __float2half_rn(v[it].y * inv)),
        pack2(__float2half_rn(v[it].z * inv), __float2half_rn(v[it].w * inv)));
  }
}

__global__ void bn_part_k(const float* __restrict__ Y, float* __restrict__ pS,
                          float* __restrict__ pQ) {
  int c = threadIdx.x, p = blockIdx.x;
  const float* base = Y + (ll)p * 64 * DM + c;
  float s = 0.f, q = 0.f;
#pragma unroll 8
  for (int r = 0; r < 64; r++) { float v = base[(ll)r * DM]; s += v; q += v * v; }
  pS[p * DM + c] = s; pQ[p * DM + c] = q;
}
__global__ void bn_finish_k(const float* __restrict__ pS, const float* __restrict__ pQ,
                            const float* __restrict__ g, const float* __restrict__ be,
                            float* __restrict__ nrm) {
  int c = threadIdx.x;
  float s = 0.f, q = 0.f;
  for (int p = 0; p < 256; p++) { s += pS[p * DM + c]; q += pQ[p * DM + c]; }
  const float invN = 1.f / (float)T_TOK;
  float mean = s * invN, var = q * invN - mean * mean;
  float a = g[c] * rsqrtf(var + EPSBN);
  nrm[c] = a; nrm[DM + c] = be[c] - mean * a;
}
__global__ void bn_apply_k(const float* __restrict__ Y, const float* __restrict__ nrm,
                           float* __restrict__ X, h16* __restrict__ Xh) {
  ll idx = ((ll)blockIdx.x * blockDim.x + threadIdx.x) * 4;
  int c = (int)(idx & (DM - 1));
  float4 v = *reinterpret_cast<const float4*>(Y + idx);
  float4 o;
  o.x = v.x * nrm[c] + nrm[DM + c];
  o.y = v.y * nrm[c + 1] + nrm[DM + c + 1];
  o.z = v.z * nrm[c + 2] + nrm[DM + c + 2];
  o.w = v.w * nrm[c + 3] + nrm[DM + c + 3];
  *reinterpret_cast<float4*>(X + idx) = o;
  *reinterpret_cast<uint2*>(Xh + idx) = make_uint2(
      pack2(__float2half_rn(o.x), __float2half_rn(o.y)),
      pack2(__float2half_rn(o.z), __float2half_rn(o.w)));
}
__global__ void copy_k(const float* __restrict__ X, float* __restrict__ out) {
  ll idx = ((ll)blockIdx.x * blockDim.x + threadIdx.x) * 4;
  *reinterpret_cast<float4*>(out + idx) = *reinterpret_cast<const float4*>(X + idx);
}

// ---------------- host ----------------
#define GETP(var, sym) void* p_##var; cudaGetSymbolAddress(&p_##var, sym)
extern "C" void kernel_launch(void* const* d_in, const int* in_sizes, int n_in,
                              void* d_out, int out_size) {
  (void)in_sizes; (void)n_in; (void)out_size;
  const int* tokens = (const int*)d_in[0];
  const float* emb = (const float*)d_in[1];
  const float *WQ = (const float*)d_in[2], *WK = (const float*)d_in[3];
  const float *WV = (const float*)d_in[4], *WO = (const float*)d_in[5];
  const float *g1 = (const float*)d_in[6], *be1 = (const float*)d_in[7];
  const float *W1 = (const float*)d_in[8], *b1 = (const float*)d_in[9];
  const float *W2 = (const float*)d_in[10], *b2 = (const float*)d_in[11];
  const float *g2 = (const float*)d_in[12], *be2 = (const float*)d_in[13];
  float* out = (float*)d_out;

  GETP(X, g_X); GETP(Y, g_Y); GETP(SC, g_SC);
  GETP(Xh, g_Xh); GETP(QKVh, g_QKVh);
  GETP(VTh, g_VTh); GETP(Ph, g_Ph);
  GETP(ATTh, g_ATTh); GETP(Fh, g_Fh);
  GETP(WQKVTh, g_WQKVTh); GETP(WOTh, g_WOTh);
  GETP(W1Th, g_W1Th); GETP(W2Th, g_W2Th);
  GETP(pS, g_partS); GETP(pQ, g_partQ); GETP(nrm, g_nrm);
  float *X = (float*)p_X, *Y = (float*)p_Y, *SC = (float*)p_SC;
  h16 *Xh = (h16*)p_Xh, *QKVh = (h16*)p_QKVh;
  h16 *VTh = (h16*)p_VTh, *Ph = (h16*)p_Ph;
  h16 *ATTh = (h16*)p_ATTh, *Fh = (h16*)p_Fh;
  h16 *WQKVTa = (h16*)p_WQKVTh, *WOTa = (h16*)p_WOTh;
  h16 *W1Ta = (h16*)p_W1Th, *W2Ta = (h16*)p_W2Th;
  float *partS = (float*)p_pS, *partQ = (float*)p_pQ, *nrm = (float*)p_nrm;

  const int SM_S128 = 2 * (128 * 80 + 128 * 80);  // 40960
  const int SM_S64  = 2 * (128 * 80 + 64 * 80);   // 30720
  cudaFuncSetAttribute(mm_gemm<128, 1, false, false, false>, cudaFuncAttributeMaxDynamicSharedMemorySize, SM_S128);
  cudaFuncSetAttribute(mm_gemm<128, 0, false, false, false>, cudaFuncAttributeMaxDynamicSharedMemorySize, SM_S128);
  cudaFuncSetAttribute(mm_gemm<64, 1, false, false, false>,  cudaFuncAttributeMaxDynamicSharedMemorySize, SM_S64);
  cudaFuncSetAttribute(mm_gemm<128, 0, false, false, true>,  cudaFuncAttributeMaxDynamicSharedMemorySize, SM_S128);
  cudaFuncSetAttribute(mm_gemm<128, 1, true, true, false>,   cudaFuncAttributeMaxDynamicSharedMemorySize, SM_S128);
  cudaFuncSetAttribute(mm_gemm<128, 0, true, false, true>,   cudaFuncAttributeMaxDynamicSharedMemorySize, SM_S128);

  const ll SS = (ll)SQ * SQ;
  dim3 tb32(32, 8);

  embed_k<<<T_TOK, 128>>>(tokens, emb, X, Xh);

  // ---- batched weight prep for ALL layers ----
  tsplit_k<<<dim3(2, 16, NLAYER * HN), tb32>>>(WQ, WQKVTa, 512, 64, HN,
      (ll)HN * 512 * 64, (ll)512 * 64, (ll)1536 * 512, (ll)64 * 512);
  tsplit_k<<<dim3(2, 16, NLAYER * HN), tb32>>>(WK, WQKVTa + 512 * 512, 512, 64, HN,
      (ll)HN * 512 * 64, (ll)512 * 64, (ll)1536 * 512, (ll)64 * 512);
  tsplit_k<<<dim3(2, 16, NLAYER * HN), tb32>>>(WV, WQKVTa + 1024 * 512, 512, 64, HN,
      (ll)HN * 512 * 64, (ll)512 * 64, (ll)1536 * 512, (ll)64 * 512);
  tsplit_k<<<dim3(16, 16, NLAYER), tb32>>>(WO, WOTa, 512, 512, 1,
      (ll)512 * 512, 0, (ll)512 * 512, 0);
  tsplit_k<<<dim3(64, 16, NLAYER), tb32>>>(W1, W1Ta, 512, 2048, 1,
      (ll)512 * 2048, 0, (ll)2048 * 512, 0);
  tsplit_k<<<dim3(16, 64, NLAYER), tb32>>>(W2, W2Ta, 2048, 512, 1,
      (ll)2048 * 512, 0, (ll)512 * 2048, 0);

  for (int i = 0; i < NLAYER; i++) {
    const h16* WQKVT = WQKVTa + (ll)i * 1536 * 512;
    const h16* WOT = WOTa + (ll)i * 512 * 512;
    const h16* W1T = W1Ta + (ll)i * 2048 * 512;
    const h16* W2T = W2Ta + (ll)i * 512 * 2048;

    // QKV: [T,512] @ [1536,512]^T -> QKVh
    mm_gemm<128, 1, false, false, false><<<dim3(128, 12, 1), 256, SM_S128>>>(
        Xh, WQKVT, nullptr, QKVh, nullptr, nullptr,
        512, 512, 512, 1536, 1.f, 1, 0, 0, 0, 0, 0, 0);

    vtrans_k<<<dim3(8, 32, 8), 256>>>(QKVh, VTh);

    // scores: per (h,b) Q@K^T/8 -> SC fp32
    mm_gemm<128, 0, false, false, false><<<dim3(4, 4, 256), 256, SM_S128>>>(
        QKVh, QKVh + 512, SC, nullptr, nullptr, nullptr,
        64, 1536, 1536, 512, 0.125f, 32,
        64, (ll)512 * 1536, 64, (ll)512 * 1536, 32 * SS, SS);

    softmax_k<<<HN * BATCH * SQ / 8, 256>>>(SC, Ph);

    // AV: per (h,b) P@VT^T -> ATTh [t][h*64+v]
    mm_gemm<64, 1, false, false, false><<<dim3(4, 1, 256), 256, SM_S64>>>(
        Ph, VTh, nullptr, ATTh, nullptr, nullptr,
        512, 512, 512, 512, 1.f, 32,
        32 * SS, SS, (ll)32 * 64 * 512, 64 * 512, 64, (ll)512 * 512);

    // O-proj + residual -> Y fp32
    mm_gemm<128, 0, false, false, true><<<dim3(128, 4, 1), 256, SM_S128>>>(
        ATTh, WOT, Y, nullptr, X, nullptr,
        512, 512, 512, 512, 1.f, 1, 0, 0, 0, 0, 0, 0);

    bn_part_k<<<256, DM>>>(Y, partS, partQ);
    bn_finish_k<<<1, DM>>>(partS, partQ, g1 + (ll)i * DM, be1 + (ll)i * DM, nrm);
    bn_apply_k<<<T_TOK * DM / 1024, 256>>>(Y, nrm, X, Xh);

    // FF1: relu(X@W1+b1) -> Fh
    mm_gemm<128, 1, true, true, false><<<dim3(128, 16, 1), 256, SM_S128>>>(
        Xh, W1T, nullptr, Fh, nullptr, b1 + (ll)i * DFF,
        512, 512, 512, 2048, 1.f, 1, 0, 0, 0, 0, 0, 0);

    // FF2 + bias + residual -> Y fp32
    mm_gemm<128, 0, true, false, true><<<dim3(128, 4, 1), 256, SM_S128>>>(
        Fh, W2T, Y, nullptr, X, b2 + (ll)i * DM,
        2048, 2048, 2048, 512, 1.f, 1, 0, 0, 0, 0, 0, 0);

    bn_part_k<<<256, DM>>>(Y, partS, partQ);
    bn_finish_k<<<1, DM>>>(partS, partQ, g2 + (ll)i * DM, be2 + (ll)i * DM, nrm);
    bn_apply_k<<<T_TOK * DM / 1024, 256>>>(Y, nrm, X, Xh);
  }

  copy_k<<<T_TOK * DM / 1024, 256>>>(X, out);
}

// round 16
// speedup vs baseline: 7.8979x; 1.0572x over previous
#include <cuda_runtime.h>
#include <cuda_fp16.h>
#include <cstdint>

#define T_TOK 16384
#define DM    512
#define DFF   2048
#define HN    8
#define SQ    512
#define BATCH 32
#define NLAYER 6
#define EPSBN 1e-5f
typedef __half h16;
typedef long long ll;

// ---------------- asm helpers (plain sm_80+ PTX) ----------------
__device__ __forceinline__ uint32_t smem_u32(const void* p) {
  uint32_t a;
  asm("{ .reg .u64 t; cvta.to.shared.u64 t, %1; cvt.u32.u64 %0, t; }" : "=r"(a) : "l"(p));
  return a;
}
__device__ __forceinline__ void ldsm4(uint32_t* r, uint32_t a) {
  asm volatile("ldmatrix.sync.aligned.m8n8.x4.shared.b16 {%0,%1,%2,%3}, [%4];"
               : "=r"(r[0]), "=r"(r[1]), "=r"(r[2]), "=r"(r[3]) : "r"(a));
}
__device__ __forceinline__ void mma16816(float* c, const uint32_t* a, const uint32_t* b) {
  asm volatile(
      "mma.sync.aligned.m16n8k16.row.col.f32.f16.f16.f32 "
      "{%0,%1,%2,%3}, {%4,%5,%6,%7}, {%8,%9}, {%0,%1,%2,%3};"
      : "+f"(c[0]), "+f"(c[1]), "+f"(c[2]), "+f"(c[3])
      : "r"(a[0]), "r"(a[1]), "r"(a[2]), "r"(a[3]), "r"(b[0]), "r"(b[1]));
}
__device__ __forceinline__ void cpa16(uint32_t s, const void* g) {
  asm volatile("cp.async.cg.shared.global [%0], [%1], 16;" :: "r"(s), "l"(g));
}
__device__ __forceinline__ uint32_t pack2(h16 a, h16 b) {
  return (uint32_t)__half_as_ushort(a) | ((uint32_t)__half_as_ushort(b) << 16);
}

// ---------------- Static scratch ----------------
__device__ float g_X[(size_t)T_TOK * DM];
__device__ float g_Y[(size_t)T_TOK * DM];
__device__ h16 g_Xh[(size_t)T_TOK * DM];
__device__ h16 g_QKVh[(size_t)T_TOK * 1536];
__device__ h16 g_VTh[(size_t)T_TOK * DM];
__device__ h16 g_Ph[(size_t)BATCH * HN * SQ * SQ];
__device__ h16 g_ATTh[(size_t)T_TOK * DM];
__device__ h16 g_Fh[(size_t)T_TOK * DFF];
__device__ h16 g_WQKVTh[(size_t)NLAYER * 1536 * 512];
__device__ h16 g_WOTh[(size_t)NLAYER * 512 * 512];
__device__ h16 g_W1Th[(size_t)NLAYER * 2048 * 512];
__device__ h16 g_W2Th[(size_t)NLAYER * 512 * 2048];
__device__ float g_partS[256 * DM], g_partQ[256 * DM], g_nrm[2 * DM];

// ------- mma.sync fp16 GEMM: C = alpha*Ah@Bh^T (+bias)(+res)(relu) -------
// A:[M,K] fp16 row-major; B:[N,K] fp16 row-major. M-tile 128, K mult of 32.
// OUTM: 0 -> fp32 C ; 1 -> fp16 Ch.
template <int BN, int OUTM, bool BIAS, bool RELU, bool RES>
__global__ void __launch_bounds__(256)
mm_gemm(const h16* __restrict__ Ah, const h16* __restrict__ Bh,
        float* __restrict__ C, h16* __restrict__ Ch,
        const float* __restrict__ Res, const float* __restrict__ bias,
        int K, int lda, int ldb, int ldc, float alpha, int zInner,
        ll sAo, ll sAi, ll sBo, ll sBi, ll sCo, ll sCi) {
  constexpr int WRM = (BN == 128) ? 2 : 4;
  constexpr int WRN = 8 / WRM;
  constexpr int WTM = 128 / WRM;
  constexpr int WTN = BN / WRN;
  constexpr int MT = WTM / 16;
  constexpr int NT = WTN / 8;
  constexpr int AB = 128 * 80;
  constexpr int BB = BN * 80;
  constexpr int SB = AB + BB;

  extern __shared__ char dynsm[];
  const uint32_t sb = smem_u32(dynsm);

  const int tid = threadIdx.x, wid = tid >> 5, lane = tid & 31;
  const int wm = wid / WRN, wn = wid % WRN;
  const int zo = blockIdx.z / zInner, zi = blockIdx.z % zInner;

  const h16* A_h = Ah + zo * sAo + zi * sAi + (ll)blockIdx.x * 128 * lda;
  const h16* B_h = Bh + zo * sBo + zi * sBi + (ll)blockIdx.y * BN * ldb;
  const ll coff = zo * sCo + zi * sCi + (ll)blockIdx.x * 128 * ldc + (ll)blockIdx.y * BN;

  float acc[MT][NT][4];
#pragma unroll
  for (int i = 0; i < MT; i++)
#pragma unroll
    for (int j = 0; j < NT; j++)
#pragma unroll
      for (int e = 0; e < 4; e++) acc[i][j][e] = 0.f;

  auto load_stage = [&](int kt, int s) {
    const int k0 = kt * 32;
    const uint32_t s0 = sb + s * SB;
#pragma unroll 2
    for (int i = tid; i < 128 * 4; i += 256) {
      const int r = i >> 2, c = i & 3;
      cpa16(s0 + (uint32_t)(r * 80 + c * 16), A_h + (ll)r * lda + k0 + c * 8);
    }
#pragma unroll
    for (int i = tid; i < BN * 4; i += 256) {
      const int r = i >> 2, c = i & 3;
      cpa16(s0 + AB + (uint32_t)(r * 80 + c * 16), B_h + (ll)r * ldb + k0 + c * 8);
    }
  };

  const int KT = K >> 5;
  load_stage(0, 0);
  asm volatile("cp.async.commit_group;");

  const uint32_t arow = (uint32_t)(lane & 15);
  const uint32_t acol = (uint32_t)((lane >> 4) * 16);
  const uint32_t brow = (uint32_t)((lane & 7) + ((lane >> 4) << 3));
  const uint32_t bcol = (uint32_t)(((lane >> 3) & 1) * 16);

  for (int kt = 0; kt < KT; kt++) {
    if (kt + 1 < KT) {
      load_stage(kt + 1, (kt + 1) & 1);
      asm volatile("cp.async.commit_group;");
      asm volatile("cp.async.wait_group 1;");
    } else {
      asm volatile("cp.async.wait_group 0;");
    }
    __syncthreads();

    const uint32_t abase = sb + (kt & 1) * SB;
    const uint32_t bbase = abase + AB;
#pragma unroll
    for (int ks = 0; ks < 2; ks++) {
      uint32_t aH[MT][4], bH[NT][2];
#pragma unroll
      for (int mt = 0; mt < MT; mt++) {
        ldsm4(aH[mt], abase + (wm * WTM + mt * 16 + arow) * 80 + ks * 32 + acol);
      }
#pragma unroll
      for (int p = 0; p < NT / 2; p++) {
        uint32_t t[4];
        ldsm4(t, bbase + (wn * WTN + p * 16 + brow) * 80 + ks * 32 + bcol);
        bH[2 * p][0] = t[0]; bH[2 * p][1] = t[1];
        bH[2 * p + 1][0] = t[2]; bH[2 * p + 1][1] = t[3];
      }
#pragma unroll
      for (int mt = 0; mt < MT; mt++)
#pragma unroll
        for (int nt = 0; nt < NT; nt++)
          mma16816(acc[mt][nt], aH[mt], bH[nt]);
    }
    __syncthreads();
  }

  // ---------------- epilogue ----------------
#pragma unroll
  for (int mt = 0; mt < MT; mt++) {
#pragma unroll
    for (int nt = 0; nt < NT; nt++) {
      const int r0 = wm * WTM + mt * 16 + (lane >> 2);
      const int cc = wn * WTN + nt * 8 + (lane & 3) * 2;
      float v0 = acc[mt][nt][0] * alpha, v1 = acc[mt][nt][1] * alpha;
      float v2 = acc[mt][nt][2] * alpha, v3 = acc[mt][nt][3] * alpha;
      if (BIAS) {
        const float b0v = bias[(ll)blockIdx.y * BN + cc];
        const float b1v = bias[(ll)blockIdx.y * BN + cc + 1];
        v0 += b0v; v2 += b0v; v1 += b1v; v3 += b1v;
      }
#pragma unroll
      for (int half = 0; half < 2; half++) {
        const int r = r0 + half * 8;
        float x0 = half ? v2 : v0, x1 = half ? v3 : v1;
        const ll go = coff + (ll)r * ldc + cc;
        if (RES) {
          const float2 rr = *reinterpret_cast<const float2*>(Res + go);
          x0 += rr.x; x1 += rr.y;
        }
        if (RELU) { x0 = fmaxf(x0, 0.f); x1 = fmaxf(x1, 0.f); }
        if (OUTM == 0) {
          *reinterpret_cast<float2*>(C + go) = make_float2(x0, x1);
        } else {
          *reinterpret_cast<uint32_t*>(Ch + go) =
              pack2(__float2half_rn(x0), __float2half_rn(x1));
        }
      }
    }
  }
}

// ------- fused attention scores + softmax: Ph = softmax(Q@K^T/8) -------
// grid (16, HN*BATCH): CTA = 32 query rows of one (h,b). 8 warps x 64 key cols.
// smem: K planes 2x(512*80), Q planes 2x(32*80), red buffers.
#define ATT_KP0 0
#define ATT_KP1 40960
#define ATT_QP0 81920
#define ATT_QP1 84480
#define ATT_RMAX 87040
#define ATT_RSUM 88064
#define ATT_SMEM 89088
__global__ void __launch_bounds__(256)
attn_k(const h16* __restrict__ QKV, h16* __restrict__ Ph) {
  extern __shared__ char dynsm[];
  const uint32_t sb = smem_u32(dynsm);
  float* redm = (float*)(dynsm + ATT_RMAX);
  float* reds = (float*)(dynsm + ATT_RSUM);

  const int tid = threadIdx.x, wid = tid >> 5, lane = tid & 31;
  const int by = blockIdx.y;            // h*32 + b
  const int h = by >> 5, b = by & 31;
  const int q0 = blockIdx.x * 32;

  // load K [512 x 64] into two 32-col planes (80B rows)
  const h16* Kbase = QKV + (ll)b * 512 * 1536 + 512 + h * 64;
#pragma unroll
  for (int i = tid; i < 512 * 8; i += 256) {
    const int kk = i >> 3, ks = (i >> 2) & 1, c = i & 3;
    cpa16(sb + (ks ? ATT_KP1 : ATT_KP0) + (uint32_t)(kk * 80 + c * 16),
          Kbase + (ll)kk * 1536 + ks * 32 + c * 8);
  }
  // load Q [32 x 64]
  const h16* Qbase = QKV + (ll)(b * 512 + q0) * 1536 + h * 64;
#pragma unroll
  for (int i = tid; i < 32 * 8; i += 256) {
    const int r = i >> 3, ks = (i >> 2) & 1, c = i & 3;
    cpa16(sb + (ks ? ATT_QP1 : ATT_QP0) + (uint32_t)(r * 80 + c * 16),
          Qbase + (ll)r * 1536 + ks * 32 + c * 8);
  }
  asm volatile("cp.async.commit_group;");
  asm volatile("cp.async.wait_group 0;");
  __syncthreads();

  const uint32_t arow = (uint32_t)(lane & 15);
  const uint32_t acol = (uint32_t)((lane >> 4) * 16);
  const uint32_t brow = (uint32_t)((lane & 7) + ((lane >> 4) << 3));
  const uint32_t bcol = (uint32_t)(((lane >> 3) & 1) * 16);

  float acc[2][8][4];
#pragma unroll
  for (int i = 0; i < 2; i++)
#pragma unroll
    for (int j = 0; j < 8; j++)
#pragma unroll
      for (int e = 0; e < 4; e++) acc[i][j][e] = 0.f;

#pragma unroll
  for (int pl = 0; pl < 2; pl++) {
    const uint32_t qb = sb + (pl ? ATT_QP1 : ATT_QP0);
    const uint32_t kb = sb + (pl ? ATT_KP1 : ATT_KP0);
#pragma unroll
    for (int ks = 0; ks < 2; ks++) {
      uint32_t aH[2][4], bH[8][2];
#pragma unroll
      for (int mt = 0; mt < 2; mt++)
        ldsm4(aH[mt], qb + (mt * 16 + arow) * 80 + ks * 32 + acol);
#pragma unroll
      for (int p = 0; p < 4; p++) {
        uint32_t t[4];
        ldsm4(t, kb + (wid * 64 + p * 16 + brow) * 80 + ks * 32 + bcol);
        bH[2 * p][0] = t[0]; bH[2 * p][1] = t[1];
        bH[2 * p + 1][0] = t[2]; bH[2 * p + 1][1] = t[3];
      }
#pragma unroll
      for (int mt = 0; mt < 2; mt++)
#pragma unroll
        for (int nt = 0; nt < 8; nt++)
          mma16816(acc[mt][nt], aH[mt], bH[nt]);
    }
  }

  // scale
#pragma unroll
  for (int i = 0; i < 2; i++)
#pragma unroll
    for (int j = 0; j < 8; j++)
#pragma unroll
      for (int e = 0; e < 4; e++) acc[i][j][e] *= 0.125f;

  // row max: local over this warp's 64 cols, then cross-warp via smem
  float wmax[2][2];
#pragma unroll
  for (int mt = 0; mt < 2; mt++)
#pragma unroll
    for (int hf = 0; hf < 2; hf++) {
      float m = -1e30f;
#pragma unroll
      for (int nt = 0; nt < 8; nt++)
        m = fmaxf(m, fmaxf(acc[mt][nt][2 * hf], acc[mt][nt][2 * hf + 1]));
      m = fmaxf(m, __shfl_xor_sync(0xffffffffu, m, 1));
      m = fmaxf(m, __shfl_xor_sync(0xffffffffu, m, 2));
      wmax[mt][hf] = m;
    }
  if ((lane & 3) == 0) {
#pragma unroll
    for (int mt = 0; mt < 2; mt++)
#pragma unroll
      for (int hf = 0; hf < 2; hf++)
        redm[(mt * 16 + (lane >> 2) + hf * 8) * 8 + wid] = wmax[mt][hf];
  }
  __syncthreads();
  float gmax[2][2];
#pragma unroll
  for (int mt = 0; mt < 2; mt++)
#pragma unroll
    for (int hf = 0; hf < 2; hf++) {
      const int row = mt * 16 + (lane >> 2) + hf * 8;
      float m = redm[row * 8 + 0];
#pragma unroll
      for (int w = 1; w < 8; w++) m = fmaxf(m, redm[row * 8 + w]);
      gmax[mt][hf] = m;
    }

  // exp + row sum
  float wsum[2][2];
#pragma unroll
  for (int mt = 0; mt < 2; mt++)
#pragma unroll
    for (int hf = 0; hf < 2; hf++) {
      float s = 0.f;
#pragma unroll
      for (int nt = 0; nt < 8; nt++) {
        float e0 = __expf(acc[mt][nt][2 * hf] - gmax[mt][hf]);
        float e1 = __expf(acc[mt][nt][2 * hf + 1] - gmax[mt][hf]);
        acc[mt][nt][2 * hf] = e0;
        acc[mt][nt][2 * hf + 1] = e1;
        s += e0 + e1;
      }
      s += __shfl_xor_sync(0xffffffffu, s, 1);
      s += __shfl_xor_sync(0xffffffffu, s, 2);
      wsum[mt][hf] = s;
    }
  if ((lane & 3) == 0) {
#pragma unroll
    for (int mt = 0; mt < 2; mt++)
#pragma unroll
      for (int hf = 0; hf < 2; hf++)
        reds[(mt * 16 + (lane >> 2) + hf * 8) * 8 + wid] = wsum[mt][hf];
  }
  __syncthreads();

  // normalize + write fp16 P
#pragma unroll
  for (int mt = 0; mt < 2; mt++)
#pragma unroll
    for (int hf = 0; hf < 2; hf++) {
      const int row = mt * 16 + (lane >> 2) + hf * 8;
      float s = 0.f;
#pragma unroll
      for (int w = 0; w < 8; w++) s += reds[row * 8 + w];
      const float inv = 1.f / s;
      const ll rb = ((ll)by * 512 + q0 + row) * 512;
#pragma unroll
      for (int nt = 0; nt < 8; nt++) {
        const int col = wid * 64 + nt * 8 + (lane & 3) * 2;
        *reinterpret_cast<uint32_t*>(Ph + rb + col) =
            pack2(__float2half_rn(acc[mt][nt][2 * hf] * inv),
                  __float2half_rn(acc[mt][nt][2 * hf + 1] * inv));
      }
    }
}

// -------- transpose + round: fp32 [R,C] -> fp16 hi [C,R]; batched 2-level z ------
__global__ void tsplit_k(const float* __restrict__ in, h16* __restrict__ oh,
                         int R, int C, int zInner,
                         ll sIno, ll sIni, ll sOuto, ll sOuti) {
  __shared__ float t[32][33];
  const int zo = blockIdx.z / zInner, zi = blockIdx.z % zInner;
  const float* I = in + zo * sIno + zi * sIni;
  h16* O = oh + zo * sOuto + zi * sOuti;
  int c0 = blockIdx.x * 32, r0 = blockIdx.y * 32;
#pragma unroll
  for (int i = 0; i < 4; i++)
    t[threadIdx.y + i * 8][threadIdx.x] =
        I[(ll)(r0 + threadIdx.y + i * 8) * C + c0 + threadIdx.x];
  __syncthreads();
#pragma unroll
  for (int i = 0; i < 4; i++) {
    int c = c0 + threadIdx.y + i * 8;
    O[(ll)c * R + r0 + threadIdx.x] = __float2half_rn(t[threadIdx.x][threadIdx.y + i * 8]);
  }
}

// -------- V transpose: QKV hi [T,1536] -> VT hi [(h,b)][64][512] --------
__global__ void vtrans_k(const h16* __restrict__ ih, h16* __restrict__ oh) {
  __shared__ h16 th[64][72];
  int h = blockIdx.x, b = blockIdx.y, s0 = blockIdx.z * 64;
  int tid = threadIdx.x;
  for (int i = tid; i < 64 * 8; i += 256) {
    int row = i >> 3, c8 = i & 7;
    ll gi = (ll)(b * 512 + s0 + row) * 1536 + 1024 + h * 64 + c8 * 8;
    *reinterpret_cast<uint4*>(&th[row][c8 * 8]) = *reinterpret_cast<const uint4*>(ih + gi);
  }
  __syncthreads();
  for (int i = tid; i < 64 * 64; i += 256) {
    int v = i >> 6, s = i & 63;
    oh[((ll)(h * 32 + b) * 64 + v) * 512 + s0 + s] = th[s][v];
  }
}

// ---------------- elementwise ----------------
__global__ void embed_k(const int* __restrict__ tok, const float* __restrict__ emb,
                        float* __restrict__ X, h16* __restrict__ Xh) {
  int t = blockIdx.x, c4 = threadIdx.x;
  float4 v = reinterpret_cast<const float4*>(emb + (ll)tok[t] * DM)[c4];
  v.x *= 8.f; v.y *= 8.f; v.z *= 8.f; v.w *= 8.f;
  ll go = (ll)t * DM + c4 * 4;
  *reinterpret_cast<float4*>(X + go) = v;
  *reinterpret_cast<uint2*>(Xh + go) = make_uint2(
      pack2(__float2half_rn(v.x), __float2half_rn(v.y)),
      pack2(__float2half_rn(v.z), __float2half_rn(v.w)));
}

__global__ void bn_part_k(const float* __restrict__ Y, float* __restrict__ pS,
                          float* __restrict__ pQ) {
  int c = threadIdx.x, p = blockIdx.x;
  const float* base = Y + (ll)p * 64 * DM + c;
  float s = 0.f, q = 0.f;
#pragma unroll 8
  for (int r = 0; r < 64; r++) { float v = base[(ll)r * DM]; s += v; q += v * v; }
  pS[p * DM + c] = s; pQ[p * DM + c] = q;
}
__global__ void bn_finish_k(const float* __restrict__ pS, const float* __restrict__ pQ,
                            const float* __restrict__ g, const float* __restrict__ be,
                            float* __restrict__ nrm) {
  int c = threadIdx.x;
  float s = 0.f, q = 0.f;
  for (int p = 0; p < 256; p++) { s += pS[p * DM + c]; q += pQ[p * DM + c]; }
  const float invN = 1.f / (float)T_TOK;
  float mean = s * invN, var = q * invN - mean * mean;
  float a = g[c] * rsqrtf(var + EPSBN);
  nrm[c] = a; nrm[DM + c] = be[c] - mean * a;
}
__global__ void bn_apply_k(const float* __restrict__ Y, const float* __restrict__ nrm,
                           float* __restrict__ X, h16* __restrict__ Xh) {
  ll idx = ((ll)blockIdx.x * blockDim.x + threadIdx.x) * 4;
  int c = (int)(idx & (DM - 1));
  float4 v = *reinterpret_cast<const float4*>(Y + idx);
  float4 o;
  o.x = v.x * nrm[c] + nrm[DM + c];
  o.y = v.y * nrm[c + 1] + nrm[DM + c + 1];
  o.z = v.z * nrm[c + 2] + nrm[DM + c + 2];
  o.w = v.w * nrm[c + 3] + nrm[DM + c + 3];
  *reinterpret_cast<float4*>(X + idx) = o;
  *reinterpret_cast<uint2*>(Xh + idx) = make_uint2(
      pack2(__float2half_rn(o.x), __float2half_rn(o.y)),
      pack2(__float2half_rn(o.z), __float2half_rn(o.w)));
}

// ---------------- host ----------------
#define GETP(var, sym) void* p_##var; cudaGetSymbolAddress(&p_##var, sym)
extern "C" void kernel_launch(void* const* d_in, const int* in_sizes, int n_in,
                              void* d_out, int out_size) {
  (void)in_sizes; (void)n_in; (void)out_size;
  const int* tokens = (const int*)d_in[0];
  const float* emb = (const float*)d_in[1];
  const float *WQ = (const float*)d_in[2], *WK = (const float*)d_in[3];
  const float *WV = (const float*)d_in[4], *WO = (const float*)d_in[5];
  const float *g1 = (const float*)d_in[6], *be1 = (const float*)d_in[7];
  const float *W1 = (const float*)d_in[8], *b1 = (const float*)d_in[9];
  const float *W2 = (const float*)d_in[10], *b2 = (const float*)d_in[11];
  const float *g2 = (const float*)d_in[12], *be2 = (const float*)d_in[13];
  float* out = (float*)d_out;

  GETP(X, g_X); GETP(Y, g_Y);
  GETP(Xh, g_Xh); GETP(QKVh, g_QKVh);
  GETP(VTh, g_VTh); GETP(Ph, g_Ph);
  GETP(ATTh, g_ATTh); GETP(Fh, g_Fh);
  GETP(WQKVTh, g_WQKVTh); GETP(WOTh, g_WOTh);
  GETP(W1Th, g_W1Th); GETP(W2Th, g_W2Th);
  GETP(pS, g_partS); GETP(pQ, g_partQ); GETP(nrm, g_nrm);
  float *X = (float*)p_X, *Y = (float*)p_Y;
  h16 *Xh = (h16*)p_Xh, *QKVh = (h16*)p_QKVh;
  h16 *VTh = (h16*)p_VTh, *Ph = (h16*)p_Ph;
  h16 *ATTh = (h16*)p_ATTh, *Fh = (h16*)p_Fh;
  h16 *WQKVTa = (h16*)p_WQKVTh, *WOTa = (h16*)p_WOTh;
  h16 *W1Ta = (h16*)p_W1Th, *W2Ta = (h16*)p_W2Th;
  float *partS = (float*)p_pS, *partQ = (float*)p_pQ, *nrm = (float*)p_nrm;

  const int SM_S128 = 2 * (128 * 80 + 128 * 80);  // 40960
  const int SM_S64  = 2 * (128 * 80 + 64 * 80);   // 30720
  cudaFuncSetAttribute(mm_gemm<128, 1, false, false, false>, cudaFuncAttributeMaxDynamicSharedMemorySize, SM_S128);
  cudaFuncSetAttribute(mm_gemm<64, 1, false, false, false>,  cudaFuncAttributeMaxDynamicSharedMemorySize, SM_S64);
  cudaFuncSetAttribute(mm_gemm<128, 0, false, false, true>,  cudaFuncAttributeMaxDynamicSharedMemorySize, SM_S128);
  cudaFuncSetAttribute(mm_gemm<128, 1, true, true, false>,   cudaFuncAttributeMaxDynamicSharedMemorySize, SM_S128);
  cudaFuncSetAttribute(mm_gemm<128, 0, true, false, true>,   cudaFuncAttributeMaxDynamicSharedMemorySize, SM_S128);
  cudaFuncSetAttribute(attn_k, cudaFuncAttributeMaxDynamicSharedMemorySize, ATT_SMEM);

  dim3 tb32(32, 8);

  embed_k<<<T_TOK, 128>>>(tokens, emb, X, Xh);

  // ---- batched weight prep for ALL layers ----
  tsplit_k<<<dim3(2, 16, NLAYER * HN), tb32>>>(WQ, WQKVTa, 512, 64, HN,
      (ll)HN * 512 * 64, (ll)512 * 64, (ll)1536 * 512, (ll)64 * 512);
  tsplit_k<<<dim3(2, 16, NLAYER * HN), tb32>>>(WK, WQKVTa + 512 * 512, 512, 64, HN,
      (ll)HN * 512 * 64, (ll)512 * 64, (ll)1536 * 512, (ll)64 * 512);
  tsplit_k<<<dim3(2, 16, NLAYER * HN), tb32>>>(WV, WQKVTa + 1024 * 512, 512, 64, HN,
      (ll)HN * 512 * 64, (ll)512 * 64, (ll)1536 * 512, (ll)64 * 512);
  tsplit_k<<<dim3(16, 16, NLAYER), tb32>>>(WO, WOTa, 512, 512, 1,
      (ll)512 * 512, 0, (ll)512 * 512, 0);
  tsplit_k<<<dim3(64, 16, NLAYER), tb32>>>(W1, W1Ta, 512, 2048, 1,
      (ll)512 * 2048, 0, (ll)2048 * 512, 0);
  tsplit_k<<<dim3(16, 64, NLAYER), tb32>>>(W2, W2Ta, 2048, 512, 1,
      (ll)2048 * 512, 0, (ll)512 * 2048, 0);

  for (int i = 0; i < NLAYER; i++) {
    const h16* WQKVT = WQKVTa + (ll)i * 1536 * 512;
    const h16* WOT = WOTa + (ll)i * 512 * 512;
    const h16* W1T = W1Ta + (ll)i * 2048 * 512;
    const h16* W2T = W2Ta + (ll)i * 512 * 2048;

    // QKV: [T,512] @ [1536,512]^T -> QKVh
    mm_gemm<128, 1, false, false, false><<<dim3(128, 12, 1), 256, SM_S128>>>(
        Xh, WQKVT, nullptr, QKVh, nullptr, nullptr,
        512, 512, 512, 1536, 1.f, 1, 0, 0, 0, 0, 0, 0);

    vtrans_k<<<dim3(8, 32, 8), 256>>>(QKVh, VTh);

    // fused scores + softmax -> Ph
    attn_k<<<dim3(16, HN * BATCH), 256, ATT_SMEM>>>(QKVh, Ph);

    // AV: per (h,b) P@VT^T -> ATTh [t][h*64+v]
    mm_gemm<64, 1, false, false, false><<<dim3(4, 1, 256), 256, SM_S64>>>(
        Ph, VTh, nullptr, ATTh, nullptr, nullptr,
        512, 512, 512, 512, 1.f, 32,
        32 * (ll)SQ * SQ, (ll)SQ * SQ, (ll)32 * 64 * 512, 64 * 512, 64, (ll)512 * 512);

    // O-proj + residual -> Y fp32
    mm_gemm<128, 0, false, false, true><<<dim3(128, 4, 1), 256, SM_S128>>>(
        ATTh, WOT, Y, nullptr, X, nullptr,
        512, 512, 512, 512, 1.f, 1, 0, 0, 0, 0, 0, 0);

    bn_part_k<<<256, DM>>>(Y, partS, partQ);
    bn_finish_k<<<1, DM>>>(partS, partQ, g1 + (ll)i * DM, be1 + (ll)i * DM, nrm);
    bn_apply_k<<<T_TOK * DM / 1024, 256>>>(Y, nrm, X, Xh);

    // FF1: relu(X@W1+b1) -> Fh
    mm_gemm<128, 1, true, true, false><<<dim3(128, 16, 1), 256, SM_S128>>>(
        Xh, W1T, nullptr, Fh, nullptr, b1 + (ll)i * DFF,
        512, 512, 512, 2048, 1.f, 1, 0, 0, 0, 0, 0, 0);

    // FF2 + bias + residual -> Y fp32
    mm_gemm<128, 0, true, false, true><<<dim3(128, 4, 1), 256, SM_S128>>>(
        Fh, W2T, Y, nullptr, X, b2 + (ll)i * DM,
        2048, 2048, 2048, 512, 1.f, 1, 0, 0, 0, 0, 0, 0);

    bn_part_k<<<256, DM>>>(Y, partS, partQ);
    bn_finish_k<<<1, DM>>>(partS, partQ, g2 + (ll)i * DM, be2 + (ll)i * DM, nrm);
    // final layer: write normalized output straight to out (skips copy kernel)
    bn_apply_k<<<T_TOK * DM / 1024, 256>>>(Y, nrm, (i == NLAYER - 1) ? out : X, Xh);
  }
}